// round 12
// baseline (speedup 1.0000x reference)
#include <cuda_runtime.h>
#include <cuda_fp16.h>
#include <cstdint>

#define N_NODES_C 50000
#define N_EDGES_C 800000

#define TPB_N 256          // node kernel: 8 warps
#define TPB_E 256          // edge kernel: 8 warps, 32 edges per warp-tile
#define NW_E 8
#define N_WT_EDGE (N_EDGES_C / 32)          // 25000 warp-tiles
#define N_WT_NODE (N_NODES_C / 16)          // 3125 warp-tiles

// Per-node layer-1 partials (scratch; no allocation allowed)
__device__ float g_P[(size_t)N_NODES_C * 128];   // nf@W1[0:64] + st@W1[160:192]
__device__ float g_Q[(size_t)N_NODES_C * 128];   // nf@W1[64:128]

// ---------------- edge kernel SMEM (bytes) ----------------
#define OFF_W1 0                          // kc=2, nc=16 : 16384
#define OFF_W2 16384                      // kc=8, nc=16 : 65536
#define OFF_W3 81920                      // kc=8, nc=8  : 32768
#define OFF_B1 114688                     // 128 f32
#define OFF_B2 115200                     // 128 f32
#define OFF_B3 115712                     // 64 f32
#define OFF_SC 115968                     // per-warp scratch: 2176 f32
#define PQ_STRIDE 132                     // PQ staging rows (16 x 132 = 2112)
#define MSG_STRIDE 68                     // msg rows (32 x 68 = 2176)
#define SC_WARP_FLOATS 2176
#define EDGE_SMEM_BYTES (OFF_SC + NW_E*SC_WARP_FLOATS*4)   // 185600

// ---------------- fused node kernel SMEM (bytes) ----------------
#define NOFF_BP  0
#define NOFF_BQ  49152
#define NOFF_BU1 81920
#define NOFF_BU2 131072
#define NOFF_UB1 163840
#define NOFF_UB2 164352
#define NODEF_SMEM_BYTES (164608)

// pack two floats into fp16x2 (low half = first arg)
static __device__ __forceinline__ uint32_t hpack2(float x0, float x1) {
    uint32_t r;
    asm("cvt.rn.f16x2.f32 %0, %1, %2;" : "=r"(r) : "f"(x1), "f"(x0));
    return r;
}
// fp16 split of a float pair -> hi fp16x2 + residual-lo fp16x2
static __device__ __forceinline__ void hsplit2(float x0, float x1,
                                               uint32_t& hi, uint32_t& lo) {
    uint32_t h = hpack2(x0, x1);
    __half2 hh = *reinterpret_cast<__half2*>(&h);
    float r0 = x0 - __half2float(__low2half(hh));
    float r1 = x1 - __half2float(__high2half(hh));
    lo = hpack2(r0, r1);
    hi = h;
}

// D += A(16x16 fp16) * B(16x8 fp16), fp32 accum
static __device__ __forceinline__ void mma_f16(float* d, const uint32_t* a,
                                               uint32_t b0, uint32_t b1) {
    asm volatile("mma.sync.aligned.m16n8k16.row.col.f32.f16.f16.f32 "
        "{%0,%1,%2,%3}, {%4,%5,%6,%7}, {%8,%9}, {%0,%1,%2,%3};"
        : "+f"(d[0]), "+f"(d[1]), "+f"(d[2]), "+f"(d[3])
        : "r"(a[0]), "r"(a[1]), "r"(a[2]), "r"(a[3]), "r"(b0), "r"(b1));
}
// 2-pass weight-split MMA: Ch += A*Bh ; Cl += A*Bl   (bw = {b0h,b1h,b0l,b1l})
static __device__ __forceinline__ void mma2s(float* Ch, float* Cl,
                                             const uint32_t* a, uint4 bw) {
    mma_f16(Ch, a, bw.x, bw.y);
    mma_f16(Cl, a, bw.z, bw.w);
}

// Stage one weight B-fragment set (fp16 hi/lo interleaved uint4) from W[k][n].
#define STAGE_FRAGS(dst_off, KC, NC, KROW_EXPR, SRC_PTR, SRC_N, STRIDE)         \
    for (int idx = tid; idx < (KC) * (NC) * 32; idx += (STRIDE)) {              \
        int T = idx & 31, nc = (idx >> 5) % (NC), kc = idx / ((NC) * 32);       \
        int n = nc * 8 + (T >> 2);                                              \
        int k0 = kc * 16 + (T & 3) * 2;                                         \
        int ka = (KROW_EXPR(k0)), kb = (KROW_EXPR(k0 + 1));                     \
        int kd = (KROW_EXPR(k0 + 8)), ke = (KROW_EXPR(k0 + 9));                 \
        float w00 = (SRC_PTR)[ka * (SRC_N) + n], w01 = (SRC_PTR)[kb * (SRC_N) + n]; \
        float w10 = (SRC_PTR)[kd * (SRC_N) + n], w11 = (SRC_PTR)[ke * (SRC_N) + n]; \
        uint32_t b0h, b0l, b1h, b1l;                                            \
        hsplit2(w00, w01, b0h, b0l);                                            \
        hsplit2(w10, w11, b1h, b1l);                                            \
        *(uint4*)(smem + (dst_off) + idx * 16) = make_uint4(b0h, b1h, b0l, b1l); \
    }

#define KR_ID(k)    (k)
#define KR_W1E(k)   (128 + (k))
#define KR_P(k)     ((k) < 64 ? (k) : (k) + 96)
#define KR_Q(k)     (64 + (k))

// ---------------------------------------------------------------------------
// Fused node kernel (unchanged from R11 — proven)
// ---------------------------------------------------------------------------
__global__ __launch_bounds__(TPB_N, 1)
void node_fused_kernel(const float* __restrict__ nf,
                       const float* __restrict__ stx,
                       const float* __restrict__ mW1,
                       const float* __restrict__ uW1, const float* __restrict__ ub1,
                       const float* __restrict__ uW2, const float* __restrict__ ub2,
                       float* __restrict__ out_node,
                       float* __restrict__ agg)
{
    extern __shared__ char smem[];
    const int tid  = threadIdx.x;
    const int w    = tid >> 5;
    const int lane = tid & 31;
    const int m    = lane & 3;
    const int qrow = lane >> 2;

    STAGE_FRAGS(NOFF_BP,  6, 16, KR_P,  mW1, 128, TPB_N)
    STAGE_FRAGS(NOFF_BQ,  4, 16, KR_Q,  mW1, 128, TPB_N)
    STAGE_FRAGS(NOFF_BU1, 6, 16, KR_ID, uW1, 128, TPB_N)
    STAGE_FRAGS(NOFF_BU2, 8, 8,  KR_ID, uW2, 64,  TPB_N)
    float* ub1s = (float*)(smem + NOFF_UB1);
    float* ub2s = (float*)(smem + NOFF_UB2);
    if (tid < 128) ub1s[tid] = ub1[tid];
    if (tid < 64)  ub2s[tid] = ub2[tid];
    __syncthreads();

    const int gw = blockIdx.x * 8 + w;
    const int gstride = gridDim.x * 8;
    const float4 z4 = make_float4(0.f, 0.f, 0.f, 0.f);

    for (int wt = gw; wt < N_WT_NODE; wt += gstride) {
        const int n0 = wt * 16 + qrow;
        const int n1 = n0 + 8;

        #pragma unroll
        for (int s = lane; s < 256; s += 32) {
            int r = s >> 4, q = s & 15;
            *(float4*)(agg + (size_t)(wt * 16 + r) * 64 + q * 4) = z4;
        }

        uint32_t xA[6][4];
        #pragma unroll
        for (int kc = 0; kc < 4; kc++) {
            float2 v0  = __ldg((const float2*)(nf + (size_t)n0 * 64 + kc * 16 + 2 * m));
            float2 v1  = __ldg((const float2*)(nf + (size_t)n1 * 64 + kc * 16 + 2 * m));
            float2 v0b = __ldg((const float2*)(nf + (size_t)n0 * 64 + kc * 16 + 8 + 2 * m));
            float2 v1b = __ldg((const float2*)(nf + (size_t)n1 * 64 + kc * 16 + 8 + 2 * m));
            xA[kc][0] = hpack2(v0.x, v0.y);
            xA[kc][1] = hpack2(v1.x, v1.y);
            xA[kc][2] = hpack2(v0b.x, v0b.y);
            xA[kc][3] = hpack2(v1b.x, v1b.y);
        }
        #pragma unroll
        for (int kc = 4; kc < 6; kc++) {
            int c = (kc - 4) * 16;
            float2 v0  = __ldg((const float2*)(stx + (size_t)n0 * 32 + c + 2 * m));
            float2 v1  = __ldg((const float2*)(stx + (size_t)n1 * 32 + c + 2 * m));
            float2 v0b = __ldg((const float2*)(stx + (size_t)n0 * 32 + c + 8 + 2 * m));
            float2 v1b = __ldg((const float2*)(stx + (size_t)n1 * 32 + c + 8 + 2 * m));
            xA[kc][0] = hpack2(v0.x, v0.y);
            xA[kc][1] = hpack2(v1.x, v1.y);
            xA[kc][2] = hpack2(v0b.x, v0b.y);
            xA[kc][3] = hpack2(v1b.x, v1b.y);
        }

        {   // P (K=96)
            #pragma unroll
            for (int np = 0; np < 8; np++) {
                float C0h[4] = {0,0,0,0}, C0l[4] = {0,0,0,0};
                float C1h[4] = {0,0,0,0}, C1l[4] = {0,0,0,0};
                #pragma unroll
                for (int kc = 0; kc < 6; kc++) {
                    uint4 b0 = *(const uint4*)(smem + NOFF_BP + (((kc * 16 + np) * 32) + lane) * 16);
                    uint4 b1 = *(const uint4*)(smem + NOFF_BP + (((kc * 16 + np + 8) * 32) + lane) * 16);
                    mma2s(C0h, C0l, xA[kc], b0);
                    mma2s(C1h, C1l, xA[kc], b1);
                }
                *(float2*)(g_P + (size_t)n0 * 128 + np * 8 + 2 * m) =
                    make_float2(C0h[0] + C0l[0], C0h[1] + C0l[1]);
                *(float2*)(g_P + (size_t)n1 * 128 + np * 8 + 2 * m) =
                    make_float2(C0h[2] + C0l[2], C0h[3] + C0l[3]);
                *(float2*)(g_P + (size_t)n0 * 128 + (np + 8) * 8 + 2 * m) =
                    make_float2(C1h[0] + C1l[0], C1h[1] + C1l[1]);
                *(float2*)(g_P + (size_t)n1 * 128 + (np + 8) * 8 + 2 * m) =
                    make_float2(C1h[2] + C1l[2], C1h[3] + C1l[3]);
            }
        }
        {   // Q (K=64)
            #pragma unroll
            for (int np = 0; np < 8; np++) {
                float C0h[4] = {0,0,0,0}, C0l[4] = {0,0,0,0};
                float C1h[4] = {0,0,0,0}, C1l[4] = {0,0,0,0};
                #pragma unroll
                for (int kc = 0; kc < 4; kc++) {
                    uint4 b0 = *(const uint4*)(smem + NOFF_BQ + (((kc * 16 + np) * 32) + lane) * 16);
                    uint4 b1 = *(const uint4*)(smem + NOFF_BQ + (((kc * 16 + np + 8) * 32) + lane) * 16);
                    mma2s(C0h, C0l, xA[kc], b0);
                    mma2s(C1h, C1l, xA[kc], b1);
                }
                *(float2*)(g_Q + (size_t)n0 * 128 + np * 8 + 2 * m) =
                    make_float2(C0h[0] + C0l[0], C0h[1] + C0l[1]);
                *(float2*)(g_Q + (size_t)n1 * 128 + np * 8 + 2 * m) =
                    make_float2(C0h[2] + C0l[2], C0h[3] + C0l[3]);
                *(float2*)(g_Q + (size_t)n0 * 128 + (np + 8) * 8 + 2 * m) =
                    make_float2(C1h[0] + C1l[0], C1h[1] + C1l[1]);
                *(float2*)(g_Q + (size_t)n1 * 128 + (np + 8) * 8 + 2 * m) =
                    make_float2(C1h[2] + C1l[2], C1h[3] + C1l[3]);
            }
        }
        uint32_t A2[8][4];
        {   // h = relu(x@uW1 + ub1)
            #pragma unroll
            for (int j = 0; j < 8; j++) {
                float2 ba = *(const float2*)(ub1s + (2 * j) * 8 + 2 * m);
                float2 bb = *(const float2*)(ub1s + (2 * j + 1) * 8 + 2 * m);
                float Cah[4] = {ba.x, ba.y, ba.x, ba.y}, Cal[4] = {0,0,0,0};
                float Cbh[4] = {bb.x, bb.y, bb.x, bb.y}, Cbl[4] = {0,0,0,0};
                #pragma unroll
                for (int kc = 0; kc < 6; kc++) {
                    uint4 ba4 = *(const uint4*)(smem + NOFF_BU1 + (((kc * 16 + 2 * j) * 32) + lane) * 16);
                    uint4 bb4 = *(const uint4*)(smem + NOFF_BU1 + (((kc * 16 + 2 * j + 1) * 32) + lane) * 16);
                    mma2s(Cah, Cal, xA[kc], ba4);
                    mma2s(Cbh, Cbl, xA[kc], bb4);
                }
                A2[j][0] = hpack2(fmaxf(Cah[0] + Cal[0], 0.f), fmaxf(Cah[1] + Cal[1], 0.f));
                A2[j][1] = hpack2(fmaxf(Cah[2] + Cal[2], 0.f), fmaxf(Cah[3] + Cal[3], 0.f));
                A2[j][2] = hpack2(fmaxf(Cbh[0] + Cbl[0], 0.f), fmaxf(Cbh[1] + Cbl[1], 0.f));
                A2[j][3] = hpack2(fmaxf(Cbh[2] + Cbl[2], 0.f), fmaxf(Cbh[3] + Cbl[3], 0.f));
            }
        }
        {   // out = nf + h@uW2 + ub2
            #pragma unroll
            for (int np = 0; np < 4; np++) {
                float2 b0v = *(const float2*)(ub2s + np * 8 + 2 * m);
                float2 b1v = *(const float2*)(ub2s + (np + 4) * 8 + 2 * m);
                float C0h[4] = {b0v.x, b0v.y, b0v.x, b0v.y}, C0l[4] = {0,0,0,0};
                float C1h[4] = {b1v.x, b1v.y, b1v.x, b1v.y}, C1l[4] = {0,0,0,0};
                #pragma unroll
                for (int kc = 0; kc < 8; kc++) {
                    uint4 b0 = *(const uint4*)(smem + NOFF_BU2 + (((kc * 8 + np) * 32) + lane) * 16);
                    uint4 b1 = *(const uint4*)(smem + NOFF_BU2 + (((kc * 8 + np + 4) * 32) + lane) * 16);
                    mma2s(C0h, C0l, A2[kc], b0);
                    mma2s(C1h, C1l, A2[kc], b1);
                }
                float2 r00 = __ldg((const float2*)(nf + (size_t)n0 * 64 + np * 8 + 2 * m));
                float2 r10 = __ldg((const float2*)(nf + (size_t)n1 * 64 + np * 8 + 2 * m));
                float2 r01 = __ldg((const float2*)(nf + (size_t)n0 * 64 + (np + 4) * 8 + 2 * m));
                float2 r11 = __ldg((const float2*)(nf + (size_t)n1 * 64 + (np + 4) * 8 + 2 * m));
                *(float2*)(out_node + (size_t)n0 * 64 + np * 8 + 2 * m) =
                    make_float2(r00.x + C0h[0] + C0l[0], r00.y + C0h[1] + C0l[1]);
                *(float2*)(out_node + (size_t)n1 * 64 + np * 8 + 2 * m) =
                    make_float2(r10.x + C0h[2] + C0l[2], r10.y + C0h[3] + C0l[3]);
                *(float2*)(out_node + (size_t)n0 * 64 + (np + 4) * 8 + 2 * m) =
                    make_float2(r01.x + C1h[0] + C1l[0], r01.y + C1h[1] + C1l[1]);
                *(float2*)(out_node + (size_t)n1 * 64 + (np + 4) * 8 + 2 * m) =
                    make_float2(r11.x + C1h[2] + C1l[2], r11.y + C1h[3] + C1l[3]);
            }
        }
    }
}

// ---------------------------------------------------------------------------
// Edge kernel: 8 warps, 32 edges per warp-tile (dual M-tile). L2/L3 weight
// fragments are loaded ONCE and shared by both M-tiles (B LDS traffic -43%).
// ---------------------------------------------------------------------------
__global__ __launch_bounds__(TPB_E, 1)
void edge_mlp_kernel(const float* __restrict__ ef,
                     const float* __restrict__ mW1, const float* __restrict__ mb1,
                     const float* __restrict__ mW2, const float* __restrict__ mb2,
                     const float* __restrict__ mW3, const float* __restrict__ mb3,
                     const int*   __restrict__ eidx,
                     float* __restrict__ agg)
{
    extern __shared__ char smem[];
    const int tid  = threadIdx.x;
    const int w    = tid >> 5;
    const int lane = tid & 31;
    const int m    = lane & 3;
    const int qrow = lane >> 2;

    STAGE_FRAGS(OFF_W1, 2, 16, KR_W1E, mW1, 128, TPB_E)
    STAGE_FRAGS(OFF_W2, 8, 16, KR_ID,  mW2, 128, TPB_E)
    STAGE_FRAGS(OFF_W3, 8, 8,  KR_ID,  mW3, 64,  TPB_E)
    float* b1s = (float*)(smem + OFF_B1);
    float* b2s = (float*)(smem + OFF_B2);
    float* b3s = (float*)(smem + OFF_B3);
    if (tid < 128) { b1s[tid] = mb1[tid]; b2s[tid] = mb2[tid]; }
    if (tid < 64)  { b3s[tid] = mb3[tid]; }
    __syncthreads();

    float* sc = (float*)(smem + OFF_SC) + w * SC_WARP_FLOATS;   // per-warp scratch
    const float4 bv1 = ((const float4*)b1s)[lane];

    const int gw = blockIdx.x * NW_E + w;
    const int gstride = gridDim.x * NW_E;

    for (int wt = gw; wt < N_WT_EDGE; wt += gstride) {
        const int base_e = wt * 32;

        // all 32 lanes hold one edge's (src,dst)
        int2 se = ((const int2*)eidx)[base_e + lane];
        __syncwarp();    // scratch reuse fence from previous tile

        // ---- prefetch ef for both M-tiles ----
        const float* eA0 = ef + (size_t)(base_e + qrow) * 32;
        const float* eA1 = ef + (size_t)(base_e + qrow + 8) * 32;
        const float* eB0 = ef + (size_t)(base_e + 16 + qrow) * 32;
        const float* eB1 = ef + (size_t)(base_e + 24 + qrow) * 32;
        uint32_t A1a[2][4], A1b[2][4];
        #pragma unroll
        for (int kc = 0; kc < 2; kc++) {
            float2 va0 = __ldg((const float2*)(eA0 + kc * 16 + 2 * m));
            float2 va1 = __ldg((const float2*)(eA1 + kc * 16 + 2 * m));
            float2 va2 = __ldg((const float2*)(eA0 + kc * 16 + 8 + 2 * m));
            float2 va3 = __ldg((const float2*)(eA1 + kc * 16 + 8 + 2 * m));
            float2 vb0 = __ldg((const float2*)(eB0 + kc * 16 + 2 * m));
            float2 vb1 = __ldg((const float2*)(eB1 + kc * 16 + 2 * m));
            float2 vb2 = __ldg((const float2*)(eB0 + kc * 16 + 8 + 2 * m));
            float2 vb3 = __ldg((const float2*)(eB1 + kc * 16 + 8 + 2 * m));
            A1a[kc][0] = hpack2(va0.x, va0.y);
            A1a[kc][1] = hpack2(va1.x, va1.y);
            A1a[kc][2] = hpack2(va2.x, va2.y);
            A1a[kc][3] = hpack2(va3.x, va3.y);
            A1b[kc][0] = hpack2(vb0.x, vb0.y);
            A1b[kc][1] = hpack2(vb1.x, vb1.y);
            A1b[kc][2] = hpack2(vb2.x, vb2.y);
            A1b[kc][3] = hpack2(vb3.x, vb3.y);
        }

        uint32_t A2a[8][4], A2b[8][4];

        // ================= M-tile A: PQ stage + L1 =================
        #pragma unroll 4
        for (int r = 0; r < 16; r++) {
            int sr = __shfl_sync(0xffffffffu, se.x, r);
            int dr = __shfl_sync(0xffffffffu, se.y, r);
            float4 pv = __ldg((const float4*)g_P + (size_t)sr * 32 + lane);
            float4 qv = __ldg((const float4*)g_Q + (size_t)dr * 32 + lane);
            float4 o;
            o.x = pv.x + qv.x + bv1.x; o.y = pv.y + qv.y + bv1.y;
            o.z = pv.z + qv.z + bv1.z; o.w = pv.w + qv.w + bv1.w;
            *(float4*)(sc + r * PQ_STRIDE + lane * 4) = o;
        }
        __syncwarp();
        #pragma unroll
        for (int j = 0; j < 4; j++) {
            int j2 = j + 4;
            float Ch[4][4], Cl[4][4];
            {
                float2 pa0 = *(const float2*)(sc + qrow * PQ_STRIDE + 16 * j + 2 * m);
                float2 pa1 = *(const float2*)(sc + (qrow + 8) * PQ_STRIDE + 16 * j + 2 * m);
                float2 pb0 = *(const float2*)(sc + qrow * PQ_STRIDE + 16 * j + 8 + 2 * m);
                float2 pb1 = *(const float2*)(sc + (qrow + 8) * PQ_STRIDE + 16 * j + 8 + 2 * m);
                float2 qa0 = *(const float2*)(sc + qrow * PQ_STRIDE + 16 * j2 + 2 * m);
                float2 qa1 = *(const float2*)(sc + (qrow + 8) * PQ_STRIDE + 16 * j2 + 2 * m);
                float2 qb0 = *(const float2*)(sc + qrow * PQ_STRIDE + 16 * j2 + 8 + 2 * m);
                float2 qb1 = *(const float2*)(sc + (qrow + 8) * PQ_STRIDE + 16 * j2 + 8 + 2 * m);
                Ch[0][0] = pa0.x; Ch[0][1] = pa0.y; Ch[0][2] = pa1.x; Ch[0][3] = pa1.y;
                Ch[1][0] = pb0.x; Ch[1][1] = pb0.y; Ch[1][2] = pb1.x; Ch[1][3] = pb1.y;
                Ch[2][0] = qa0.x; Ch[2][1] = qa0.y; Ch[2][2] = qa1.x; Ch[2][3] = qa1.y;
                Ch[3][0] = qb0.x; Ch[3][1] = qb0.y; Ch[3][2] = qb1.x; Ch[3][3] = qb1.y;
                #pragma unroll
                for (int c = 0; c < 4; c++)
                    #pragma unroll
                    for (int i = 0; i < 4; i++) Cl[c][i] = 0.f;
            }
            #pragma unroll
            for (int kc = 0; kc < 2; kc++) {
                uint4 b0 = *(const uint4*)(smem + OFF_W1 + (((kc * 16 + 2 * j) * 32) + lane) * 16);
                uint4 b1 = *(const uint4*)(smem + OFF_W1 + (((kc * 16 + 2 * j + 1) * 32) + lane) * 16);
                uint4 b2 = *(const uint4*)(smem + OFF_W1 + (((kc * 16 + 2 * j2) * 32) + lane) * 16);
                uint4 b3 = *(const uint4*)(smem + OFF_W1 + (((kc * 16 + 2 * j2 + 1) * 32) + lane) * 16);
                mma2s(Ch[0], Cl[0], A1a[kc], b0);
                mma2s(Ch[1], Cl[1], A1a[kc], b1);
                mma2s(Ch[2], Cl[2], A1a[kc], b2);
                mma2s(Ch[3], Cl[3], A1a[kc], b3);
            }
            A2a[j][0]  = hpack2(fmaxf(Ch[0][0] + Cl[0][0], 0.f), fmaxf(Ch[0][1] + Cl[0][1], 0.f));
            A2a[j][1]  = hpack2(fmaxf(Ch[0][2] + Cl[0][2], 0.f), fmaxf(Ch[0][3] + Cl[0][3], 0.f));
            A2a[j][2]  = hpack2(fmaxf(Ch[1][0] + Cl[1][0], 0.f), fmaxf(Ch[1][1] + Cl[1][1], 0.f));
            A2a[j][3]  = hpack2(fmaxf(Ch[1][2] + Cl[1][2], 0.f), fmaxf(Ch[1][3] + Cl[1][3], 0.f));
            A2a[j2][0] = hpack2(fmaxf(Ch[2][0] + Cl[2][0], 0.f), fmaxf(Ch[2][1] + Cl[2][1], 0.f));
            A2a[j2][1] = hpack2(fmaxf(Ch[2][2] + Cl[2][2], 0.f), fmaxf(Ch[2][3] + Cl[2][3], 0.f));
            A2a[j2][2] = hpack2(fmaxf(Ch[3][0] + Cl[3][0], 0.f), fmaxf(Ch[3][1] + Cl[3][1], 0.f));
            A2a[j2][3] = hpack2(fmaxf(Ch[3][2] + Cl[3][2], 0.f), fmaxf(Ch[3][3] + Cl[3][3], 0.f));
        }
        __syncwarp();

        // ================= M-tile B: PQ stage + L1 =================
        #pragma unroll 4
        for (int r = 0; r < 16; r++) {
            int sr = __shfl_sync(0xffffffffu, se.x, 16 + r);
            int dr = __shfl_sync(0xffffffffu, se.y, 16 + r);
            float4 pv = __ldg((const float4*)g_P + (size_t)sr * 32 + lane);
            float4 qv = __ldg((const float4*)g_Q + (size_t)dr * 32 + lane);
            float4 o;
            o.x = pv.x + qv.x + bv1.x; o.y = pv.y + qv.y + bv1.y;
            o.z = pv.z + qv.z + bv1.z; o.w = pv.w + qv.w + bv1.w;
            *(float4*)(sc + r * PQ_STRIDE + lane * 4) = o;
        }
        __syncwarp();
        #pragma unroll
        for (int j = 0; j < 4; j++) {
            int j2 = j + 4;
            float Ch[4][4], Cl[4][4];
            {
                float2 pa0 = *(const float2*)(sc + qrow * PQ_STRIDE + 16 * j + 2 * m);
                float2 pa1 = *(const float2*)(sc + (qrow + 8) * PQ_STRIDE + 16 * j + 2 * m);
                float2 pb0 = *(const float2*)(sc + qrow * PQ_STRIDE + 16 * j + 8 + 2 * m);
                float2 pb1 = *(const float2*)(sc + (qrow + 8) * PQ_STRIDE + 16 * j + 8 + 2 * m);
                float2 qa0 = *(const float2*)(sc + qrow * PQ_STRIDE + 16 * j2 + 2 * m);
                float2 qa1 = *(const float2*)(sc + (qrow + 8) * PQ_STRIDE + 16 * j2 + 2 * m);
                float2 qb0 = *(const float2*)(sc + qrow * PQ_STRIDE + 16 * j2 + 8 + 2 * m);
                float2 qb1 = *(const float2*)(sc + (qrow + 8) * PQ_STRIDE + 16 * j2 + 8 + 2 * m);
                Ch[0][0] = pa0.x; Ch[0][1] = pa0.y; Ch[0][2] = pa1.x; Ch[0][3] = pa1.y;
                Ch[1][0] = pb0.x; Ch[1][1] = pb0.y; Ch[1][2] = pb1.x; Ch[1][3] = pb1.y;
                Ch[2][0] = qa0.x; Ch[2][1] = qa0.y; Ch[2][2] = qa1.x; Ch[2][3] = qa1.y;
                Ch[3][0] = qb0.x; Ch[3][1] = qb0.y; Ch[3][2] = qb1.x; Ch[3][3] = qb1.y;
                #pragma unroll
                for (int c = 0; c < 4; c++)
                    #pragma unroll
                    for (int i = 0; i < 4; i++) Cl[c][i] = 0.f;
            }
            #pragma unroll
            for (int kc = 0; kc < 2; kc++) {
                uint4 b0 = *(const uint4*)(smem + OFF_W1 + (((kc * 16 + 2 * j) * 32) + lane) * 16);
                uint4 b1 = *(const uint4*)(smem + OFF_W1 + (((kc * 16 + 2 * j + 1) * 32) + lane) * 16);
                uint4 b2 = *(const uint4*)(smem + OFF_W1 + (((kc * 16 + 2 * j2) * 32) + lane) * 16);
                uint4 b3 = *(const uint4*)(smem + OFF_W1 + (((kc * 16 + 2 * j2 + 1) * 32) + lane) * 16);
                mma2s(Ch[0], Cl[0], A1b[kc], b0);
                mma2s(Ch[1], Cl[1], A1b[kc], b1);
                mma2s(Ch[2], Cl[2], A1b[kc], b2);
                mma2s(Ch[3], Cl[3], A1b[kc], b3);
            }
            A2b[j][0]  = hpack2(fmaxf(Ch[0][0] + Cl[0][0], 0.f), fmaxf(Ch[0][1] + Cl[0][1], 0.f));
            A2b[j][1]  = hpack2(fmaxf(Ch[0][2] + Cl[0][2], 0.f), fmaxf(Ch[0][3] + Cl[0][3], 0.f));
            A2b[j][2]  = hpack2(fmaxf(Ch[1][0] + Cl[1][0], 0.f), fmaxf(Ch[1][1] + Cl[1][1], 0.f));
            A2b[j][3]  = hpack2(fmaxf(Ch[1][2] + Cl[1][2], 0.f), fmaxf(Ch[1][3] + Cl[1][3], 0.f));
            A2b[j2][0] = hpack2(fmaxf(Ch[2][0] + Cl[2][0], 0.f), fmaxf(Ch[2][1] + Cl[2][1], 0.f));
            A2b[j2][1] = hpack2(fmaxf(Ch[2][2] + Cl[2][2], 0.f), fmaxf(Ch[2][3] + Cl[2][3], 0.f));
            A2b[j2][2] = hpack2(fmaxf(Ch[3][0] + Cl[3][0], 0.f), fmaxf(Ch[3][1] + Cl[3][1], 0.f));
            A2b[j2][3] = hpack2(fmaxf(Ch[3][2] + Cl[3][2], 0.f), fmaxf(Ch[3][3] + Cl[3][3], 0.f));
        }

        // ================= L2 dual-M: shared B fragments =================
        uint32_t A3a[8][4], A3b[8][4];
        #pragma unroll
        for (int j = 0; j < 8; j++) {
            float2 ba2 = *(const float2*)(b2s + (2 * j) * 8 + 2 * m);
            float2 bb2 = *(const float2*)(b2s + (2 * j + 1) * 8 + 2 * m);
            float CAah[4] = {ba2.x, ba2.y, ba2.x, ba2.y}, CAal[4] = {0,0,0,0};
            float CAbh[4] = {bb2.x, bb2.y, bb2.x, bb2.y}, CAbl[4] = {0,0,0,0};
            float CBah[4] = {ba2.x, ba2.y, ba2.x, ba2.y}, CBal[4] = {0,0,0,0};
            float CBbh[4] = {bb2.x, bb2.y, bb2.x, bb2.y}, CBbl[4] = {0,0,0,0};
            #pragma unroll
            for (int kc = 0; kc < 8; kc++) {
                uint4 b0 = *(const uint4*)(smem + OFF_W2 + (((kc * 16 + 2 * j) * 32) + lane) * 16);
                uint4 b1 = *(const uint4*)(smem + OFF_W2 + (((kc * 16 + 2 * j + 1) * 32) + lane) * 16);
                mma2s(CAah, CAal, A2a[kc], b0);
                mma2s(CAbh, CAbl, A2a[kc], b1);
                mma2s(CBah, CBal, A2b[kc], b0);
                mma2s(CBbh, CBbl, A2b[kc], b1);
            }
            A3a[j][0] = hpack2(fmaxf(CAah[0] + CAal[0], 0.f), fmaxf(CAah[1] + CAal[1], 0.f));
            A3a[j][1] = hpack2(fmaxf(CAah[2] + CAal[2], 0.f), fmaxf(CAah[3] + CAal[3], 0.f));
            A3a[j][2] = hpack2(fmaxf(CAbh[0] + CAbl[0], 0.f), fmaxf(CAbh[1] + CAbl[1], 0.f));
            A3a[j][3] = hpack2(fmaxf(CAbh[2] + CAbl[2], 0.f), fmaxf(CAbh[3] + CAbl[3], 0.f));
            A3b[j][0] = hpack2(fmaxf(CBah[0] + CBal[0], 0.f), fmaxf(CBah[1] + CBal[1], 0.f));
            A3b[j][1] = hpack2(fmaxf(CBah[2] + CBal[2], 0.f), fmaxf(CBah[3] + CBal[3], 0.f));
            A3b[j][2] = hpack2(fmaxf(CBbh[0] + CBbl[0], 0.f), fmaxf(CBbh[1] + CBbl[1], 0.f));
            A3b[j][3] = hpack2(fmaxf(CBbh[2] + CBbl[2], 0.f), fmaxf(CBbh[3] + CBbl[3], 0.f));
        }

        // ================= L3 dual-M: shared B fragments -> msg =================
        __syncwarp();   // L1 scratch reads complete before msg overwrite
        #pragma unroll
        for (int nc = 0; nc < 4; nc++) {
            int nc2 = nc + 4;
            float2 b0v = *(const float2*)(b3s + nc * 8 + 2 * m);
            float2 b1v = *(const float2*)(b3s + nc2 * 8 + 2 * m);
            float CAah[4] = {b0v.x, b0v.y, b0v.x, b0v.y}, CAal[4] = {0,0,0,0};
            float CAbh[4] = {b1v.x, b1v.y, b1v.x, b1v.y}, CAbl[4] = {0,0,0,0};
            float CBah[4] = {b0v.x, b0v.y, b0v.x, b0v.y}, CBal[4] = {0,0,0,0};
            float CBbh[4] = {b1v.x, b1v.y, b1v.x, b1v.y}, CBbl[4] = {0,0,0,0};
            #pragma unroll
            for (int kc = 0; kc < 8; kc++) {
                uint4 b0 = *(const uint4*)(smem + OFF_W3 + (((kc * 8 + nc) * 32) + lane) * 16);
                uint4 b1 = *(const uint4*)(smem + OFF_W3 + (((kc * 8 + nc2) * 32) + lane) * 16);
                mma2s(CAah, CAal, A3a[kc], b0);
                mma2s(CAbh, CAbl, A3a[kc], b1);
                mma2s(CBah, CBal, A3b[kc], b0);
                mma2s(CBbh, CBbl, A3b[kc], b1);
            }
            // tile A rows 0..15, tile B rows 16..31 (msg stride 68)
            *(float2*)(sc + qrow * MSG_STRIDE + 8 * nc + 2 * m) =
                make_float2(CAah[0] + CAal[0], CAah[1] + CAal[1]);
            *(float2*)(sc + (qrow + 8) * MSG_STRIDE + 8 * nc + 2 * m) =
                make_float2(CAah[2] + CAal[2], CAah[3] + CAal[3]);
            *(float2*)(sc + qrow * MSG_STRIDE + 8 * nc2 + 2 * m) =
                make_float2(CAbh[0] + CAbl[0], CAbh[1] + CAbl[1]);
            *(float2*)(sc + (qrow + 8) * MSG_STRIDE + 8 * nc2 + 2 * m) =
                make_float2(CAbh[2] + CAbl[2], CAbh[3] + CAbl[3]);
            *(float2*)(sc + (16 + qrow) * MSG_STRIDE + 8 * nc + 2 * m) =
                make_float2(CBah[0] + CBal[0], CBah[1] + CBal[1]);
            *(float2*)(sc + (24 + qrow) * MSG_STRIDE + 8 * nc + 2 * m) =
                make_float2(CBah[2] + CBal[2], CBah[3] + CBal[3]);
            *(float2*)(sc + (16 + qrow) * MSG_STRIDE + 8 * nc2 + 2 * m) =
                make_float2(CBbh[0] + CBbl[0], CBbh[1] + CBbl[1]);
            *(float2*)(sc + (24 + qrow) * MSG_STRIDE + 8 * nc2 + 2 * m) =
                make_float2(CBbh[2] + CBbl[2], CBbh[3] + CBbl[3]);
        }
        __syncwarp();

        // ---- scatter: 32 edges x 16 float4 atomics ----
        #pragma unroll
        for (int it = 0; it < 16; it++) {
            int slot = it * 32 + lane;
            int e = slot >> 4, q = slot & 15;
            float4 v = *(const float4*)(sc + e * MSG_STRIDE + q * 4);
            int dn = __shfl_sync(0xffffffffu, se.y, e);
            atomicAdd(((float4*)(agg + (size_t)dn * 64)) + q, v);
        }
    }
}

extern "C" void kernel_launch(void* const* d_in, const int* in_sizes, int n_in,
                              void* d_out, int out_size)
{
    const float* nf  = (const float*)d_in[0];
    const float* ef  = (const float*)d_in[1];
    const float* stx = (const float*)d_in[2];
    const float* mW1 = (const float*)d_in[3];
    const float* mb1 = (const float*)d_in[4];
    const float* mW2 = (const float*)d_in[5];
    const float* mb2 = (const float*)d_in[6];
    const float* mW3 = (const float*)d_in[7];
    const float* mb3 = (const float*)d_in[8];
    const float* uW1 = (const float*)d_in[9];
    const float* ub1 = (const float*)d_in[10];
    const float* uW2 = (const float*)d_in[11];
    const float* ub2 = (const float*)d_in[12];
    const int*  eidx = (const int*)d_in[13];

    float* out_node = (float*)d_out;
    float* agg      = out_node + (size_t)N_NODES_C * 64;

    cudaFuncSetAttribute(edge_mlp_kernel,
                         cudaFuncAttributeMaxDynamicSharedMemorySize, EDGE_SMEM_BYTES);
    cudaFuncSetAttribute(node_fused_kernel,
                         cudaFuncAttributeMaxDynamicSharedMemorySize, NODEF_SMEM_BYTES);

    int dev = 0;
    cudaGetDevice(&dev);
    int sms = 148;
    cudaDeviceGetAttribute(&sms, cudaDevAttrMultiProcessorCount, dev);

    node_fused_kernel<<<sms, TPB_N, NODEF_SMEM_BYTES>>>(nf, stx, mW1, uW1, ub1, uW2, ub2,
                                                        out_node, agg);
    edge_mlp_kernel<<<sms, TPB_E, EDGE_SMEM_BYTES>>>(ef, mW1, mb1, mW2, mb2,
                                                     mW3, mb3, eidx, agg);
}

// round 13
// speedup vs baseline: 1.4599x; 1.4599x over previous
#include <cuda_runtime.h>
#include <cuda_fp16.h>
#include <cstdint>

#define N_NODES_C 50000
#define N_EDGES_C 800000

#define TPB_N 256          // node kernel: 8 warps
#define TPB_E 384          // edge kernel: 12 warps
#define NW_E 12
#define N_WT_EDGE (N_EDGES_C / 16)          // 50000 warp-tiles
#define N_WT_NODE (N_NODES_C / 16)          // 3125 warp-tiles

// Per-node layer-1 partials (scratch; no allocation allowed)
__device__ float g_P[(size_t)N_NODES_C * 128];   // nf@W1[0:64] + st@W1[160:192]
__device__ float g_Q[(size_t)N_NODES_C * 128];   // nf@W1[64:128]

// ---------------- edge kernel SMEM (bytes): 1-pass fp16, nc-pair packed ----
#define OFF_W1 0                          // kc=2, ncp=8 : 2*8*32*16  = 8192
#define OFF_W2 8192                       // kc=8, ncp=8 : 8*8*32*16  = 32768
#define OFF_W3 40960                      // kc=8, ncp=4 : 8*4*32*16  = 16384
#define OFF_B1 57344                      // 128 f32
#define OFF_B2 57856                      // 128 f32
#define OFF_B3 58368                      // 64 f32
#define OFF_SC 58624                      // 12 warps * 16 rows * 132 f32
#define PQ_STRIDE 132
#define MSG_STRIDE 72
#define PQ_WARP_BYTES (16*PQ_STRIDE*4)    // 8448
#define EDGE_SMEM_BYTES (OFF_SC + NW_E*PQ_WARP_BYTES)   // 160000

// ---------------- fused node kernel SMEM (bytes): 2-pass (accuracy) --------
#define NOFF_BP  0
#define NOFF_BQ  49152
#define NOFF_BU1 81920
#define NOFF_BU2 131072
#define NOFF_UB1 163840
#define NOFF_UB2 164352
#define NODEF_SMEM_BYTES (164608)

// pack two floats into fp16x2 (low half = first arg)
static __device__ __forceinline__ uint32_t hpack2(float x0, float x1) {
    uint32_t r;
    asm("cvt.rn.f16x2.f32 %0, %1, %2;" : "=r"(r) : "f"(x1), "f"(x0));
    return r;
}
// fp16 split of a float pair -> hi fp16x2 + residual-lo fp16x2
static __device__ __forceinline__ void hsplit2(float x0, float x1,
                                               uint32_t& hi, uint32_t& lo) {
    uint32_t h = hpack2(x0, x1);
    __half2 hh = *reinterpret_cast<__half2*>(&h);
    float r0 = x0 - __half2float(__low2half(hh));
    float r1 = x1 - __half2float(__high2half(hh));
    lo = hpack2(r0, r1);
    hi = h;
}

// D += A(16x16 fp16) * B(16x8 fp16), fp32 accum
static __device__ __forceinline__ void mma_f16(float* d, const uint32_t* a,
                                               uint32_t b0, uint32_t b1) {
    asm volatile("mma.sync.aligned.m16n8k16.row.col.f32.f16.f16.f32 "
        "{%0,%1,%2,%3}, {%4,%5,%6,%7}, {%8,%9}, {%0,%1,%2,%3};"
        : "+f"(d[0]), "+f"(d[1]), "+f"(d[2]), "+f"(d[3])
        : "r"(a[0]), "r"(a[1]), "r"(a[2]), "r"(a[3]), "r"(b0), "r"(b1));
}
// 2-pass weight-split MMA (node kernel): Ch += A*Bh ; Cl += A*Bl
static __device__ __forceinline__ void mma2s(float* Ch, float* Cl,
                                             const uint32_t* a, uint4 bw) {
    mma_f16(Ch, a, bw.x, bw.y);
    mma_f16(Cl, a, bw.z, bw.w);
}

// 2-pass fragment staging (node kernel): uint4 = {b0h,b1h,b0l,b1l} per nc
#define STAGE_FRAGS2(dst_off, KC, NC, KROW_EXPR, SRC_PTR, SRC_N, STRIDE)        \
    for (int idx = tid; idx < (KC) * (NC) * 32; idx += (STRIDE)) {              \
        int T = idx & 31, nc = (idx >> 5) % (NC), kc = idx / ((NC) * 32);       \
        int n = nc * 8 + (T >> 2);                                              \
        int k0 = kc * 16 + (T & 3) * 2;                                         \
        int ka = (KROW_EXPR(k0)), kb = (KROW_EXPR(k0 + 1));                     \
        int kd = (KROW_EXPR(k0 + 8)), ke = (KROW_EXPR(k0 + 9));                 \
        float w00 = (SRC_PTR)[ka * (SRC_N) + n], w01 = (SRC_PTR)[kb * (SRC_N) + n]; \
        float w10 = (SRC_PTR)[kd * (SRC_N) + n], w11 = (SRC_PTR)[ke * (SRC_N) + n]; \
        uint32_t b0h, b0l, b1h, b1l;                                            \
        hsplit2(w00, w01, b0h, b0l);                                            \
        hsplit2(w10, w11, b1h, b1l);                                            \
        *(uint4*)(smem + (dst_off) + idx * 16) = make_uint4(b0h, b1h, b0l, b1l); \
    }

// 1-pass fragment staging (edge kernel): uint4 packs TWO adjacent nc:
//   {b0(2p), b1(2p), b0(2p+1), b1(2p+1)}   (p = nc pair index)
#define STAGE_FRAGS1(dst_off, KC, NCP, KROW_EXPR, SRC_PTR, SRC_N, STRIDE)       \
    for (int idx = tid; idx < (KC) * (NCP) * 32; idx += (STRIDE)) {             \
        int T = idx & 31, p = (idx >> 5) % (NCP), kc = idx / ((NCP) * 32);      \
        int n0 = (2 * p) * 8 + (T >> 2);                                        \
        int n1 = n0 + 8;                                                        \
        int k0 = kc * 16 + (T & 3) * 2;                                         \
        int ka = (KROW_EXPR(k0)), kb = (KROW_EXPR(k0 + 1));                     \
        int kd = (KROW_EXPR(k0 + 8)), ke = (KROW_EXPR(k0 + 9));                 \
        uint32_t a0 = hpack2((SRC_PTR)[ka * (SRC_N) + n0], (SRC_PTR)[kb * (SRC_N) + n0]); \
        uint32_t a1 = hpack2((SRC_PTR)[kd * (SRC_N) + n0], (SRC_PTR)[ke * (SRC_N) + n0]); \
        uint32_t c0 = hpack2((SRC_PTR)[ka * (SRC_N) + n1], (SRC_PTR)[kb * (SRC_N) + n1]); \
        uint32_t c1 = hpack2((SRC_PTR)[kd * (SRC_N) + n1], (SRC_PTR)[ke * (SRC_N) + n1]); \
        *(uint4*)(smem + (dst_off) + idx * 16) = make_uint4(a0, a1, c0, c1);    \
    }

#define KR_ID(k)    (k)
#define KR_W1E(k)   (128 + (k))
#define KR_P(k)     ((k) < 64 ? (k) : (k) + 96)
#define KR_Q(k)     (64 + (k))

// ---------------------------------------------------------------------------
// Fused node kernel (unchanged from R11 — proven, 2-pass precision)
// ---------------------------------------------------------------------------
__global__ __launch_bounds__(TPB_N, 1)
void node_fused_kernel(const float* __restrict__ nf,
                       const float* __restrict__ stx,
                       const float* __restrict__ mW1,
                       const float* __restrict__ uW1, const float* __restrict__ ub1,
                       const float* __restrict__ uW2, const float* __restrict__ ub2,
                       float* __restrict__ out_node,
                       float* __restrict__ agg)
{
    extern __shared__ char smem[];
    const int tid  = threadIdx.x;
    const int w    = tid >> 5;
    const int lane = tid & 31;
    const int m    = lane & 3;
    const int qrow = lane >> 2;

    STAGE_FRAGS2(NOFF_BP,  6, 16, KR_P,  mW1, 128, TPB_N)
    STAGE_FRAGS2(NOFF_BQ,  4, 16, KR_Q,  mW1, 128, TPB_N)
    STAGE_FRAGS2(NOFF_BU1, 6, 16, KR_ID, uW1, 128, TPB_N)
    STAGE_FRAGS2(NOFF_BU2, 8, 8,  KR_ID, uW2, 64,  TPB_N)
    float* ub1s = (float*)(smem + NOFF_UB1);
    float* ub2s = (float*)(smem + NOFF_UB2);
    if (tid < 128) ub1s[tid] = ub1[tid];
    if (tid < 64)  ub2s[tid] = ub2[tid];
    __syncthreads();

    const int gw = blockIdx.x * 8 + w;
    const int gstride = gridDim.x * 8;
    const float4 z4 = make_float4(0.f, 0.f, 0.f, 0.f);

    for (int wt = gw; wt < N_WT_NODE; wt += gstride) {
        const int n0 = wt * 16 + qrow;
        const int n1 = n0 + 8;

        #pragma unroll
        for (int s = lane; s < 256; s += 32) {
            int r = s >> 4, q = s & 15;
            *(float4*)(agg + (size_t)(wt * 16 + r) * 64 + q * 4) = z4;
        }

        uint32_t xA[6][4];
        #pragma unroll
        for (int kc = 0; kc < 4; kc++) {
            float2 v0  = __ldg((const float2*)(nf + (size_t)n0 * 64 + kc * 16 + 2 * m));
            float2 v1  = __ldg((const float2*)(nf + (size_t)n1 * 64 + kc * 16 + 2 * m));
            float2 v0b = __ldg((const float2*)(nf + (size_t)n0 * 64 + kc * 16 + 8 + 2 * m));
            float2 v1b = __ldg((const float2*)(nf + (size_t)n1 * 64 + kc * 16 + 8 + 2 * m));
            xA[kc][0] = hpack2(v0.x, v0.y);
            xA[kc][1] = hpack2(v1.x, v1.y);
            xA[kc][2] = hpack2(v0b.x, v0b.y);
            xA[kc][3] = hpack2(v1b.x, v1b.y);
        }
        #pragma unroll
        for (int kc = 4; kc < 6; kc++) {
            int c = (kc - 4) * 16;
            float2 v0  = __ldg((const float2*)(stx + (size_t)n0 * 32 + c + 2 * m));
            float2 v1  = __ldg((const float2*)(stx + (size_t)n1 * 32 + c + 2 * m));
            float2 v0b = __ldg((const float2*)(stx + (size_t)n0 * 32 + c + 8 + 2 * m));
            float2 v1b = __ldg((const float2*)(stx + (size_t)n1 * 32 + c + 8 + 2 * m));
            xA[kc][0] = hpack2(v0.x, v0.y);
            xA[kc][1] = hpack2(v1.x, v1.y);
            xA[kc][2] = hpack2(v0b.x, v0b.y);
            xA[kc][3] = hpack2(v1b.x, v1b.y);
        }

        {   // P (K=96)
            #pragma unroll
            for (int np = 0; np < 8; np++) {
                float C0h[4] = {0,0,0,0}, C0l[4] = {0,0,0,0};
                float C1h[4] = {0,0,0,0}, C1l[4] = {0,0,0,0};
                #pragma unroll
                for (int kc = 0; kc < 6; kc++) {
                    uint4 b0 = *(const uint4*)(smem + NOFF_BP + (((kc * 16 + np) * 32) + lane) * 16);
                    uint4 b1 = *(const uint4*)(smem + NOFF_BP + (((kc * 16 + np + 8) * 32) + lane) * 16);
                    mma2s(C0h, C0l, xA[kc], b0);
                    mma2s(C1h, C1l, xA[kc], b1);
                }
                *(float2*)(g_P + (size_t)n0 * 128 + np * 8 + 2 * m) =
                    make_float2(C0h[0] + C0l[0], C0h[1] + C0l[1]);
                *(float2*)(g_P + (size_t)n1 * 128 + np * 8 + 2 * m) =
                    make_float2(C0h[2] + C0l[2], C0h[3] + C0l[3]);
                *(float2*)(g_P + (size_t)n0 * 128 + (np + 8) * 8 + 2 * m) =
                    make_float2(C1h[0] + C1l[0], C1h[1] + C1l[1]);
                *(float2*)(g_P + (size_t)n1 * 128 + (np + 8) * 8 + 2 * m) =
                    make_float2(C1h[2] + C1l[2], C1h[3] + C1l[3]);
            }
        }
        {   // Q (K=64)
            #pragma unroll
            for (int np = 0; np < 8; np++) {
                float C0h[4] = {0,0,0,0}, C0l[4] = {0,0,0,0};
                float C1h[4] = {0,0,0,0}, C1l[4] = {0,0,0,0};
                #pragma unroll
                for (int kc = 0; kc < 4; kc++) {
                    uint4 b0 = *(const uint4*)(smem + NOFF_BQ + (((kc * 16 + np) * 32) + lane) * 16);
                    uint4 b1 = *(const uint4*)(smem + NOFF_BQ + (((kc * 16 + np + 8) * 32) + lane) * 16);
                    mma2s(C0h, C0l, xA[kc], b0);
                    mma2s(C1h, C1l, xA[kc], b1);
                }
                *(float2*)(g_Q + (size_t)n0 * 128 + np * 8 + 2 * m) =
                    make_float2(C0h[0] + C0l[0], C0h[1] + C0l[1]);
                *(float2*)(g_Q + (size_t)n1 * 128 + np * 8 + 2 * m) =
                    make_float2(C0h[2] + C0l[2], C0h[3] + C0l[3]);
                *(float2*)(g_Q + (size_t)n0 * 128 + (np + 8) * 8 + 2 * m) =
                    make_float2(C1h[0] + C1l[0], C1h[1] + C1l[1]);
                *(float2*)(g_Q + (size_t)n1 * 128 + (np + 8) * 8 + 2 * m) =
                    make_float2(C1h[2] + C1l[2], C1h[3] + C1l[3]);
            }
        }
        uint32_t A2[8][4];
        {   // h = relu(x@uW1 + ub1)
            #pragma unroll
            for (int j = 0; j < 8; j++) {
                float2 ba = *(const float2*)(ub1s + (2 * j) * 8 + 2 * m);
                float2 bb = *(const float2*)(ub1s + (2 * j + 1) * 8 + 2 * m);
                float Cah[4] = {ba.x, ba.y, ba.x, ba.y}, Cal[4] = {0,0,0,0};
                float Cbh[4] = {bb.x, bb.y, bb.x, bb.y}, Cbl[4] = {0,0,0,0};
                #pragma unroll
                for (int kc = 0; kc < 6; kc++) {
                    uint4 ba4 = *(const uint4*)(smem + NOFF_BU1 + (((kc * 16 + 2 * j) * 32) + lane) * 16);
                    uint4 bb4 = *(const uint4*)(smem + NOFF_BU1 + (((kc * 16 + 2 * j + 1) * 32) + lane) * 16);
                    mma2s(Cah, Cal, xA[kc], ba4);
                    mma2s(Cbh, Cbl, xA[kc], bb4);
                }
                A2[j][0] = hpack2(fmaxf(Cah[0] + Cal[0], 0.f), fmaxf(Cah[1] + Cal[1], 0.f));
                A2[j][1] = hpack2(fmaxf(Cah[2] + Cal[2], 0.f), fmaxf(Cah[3] + Cal[3], 0.f));
                A2[j][2] = hpack2(fmaxf(Cbh[0] + Cbl[0], 0.f), fmaxf(Cbh[1] + Cbl[1], 0.f));
                A2[j][3] = hpack2(fmaxf(Cbh[2] + Cbl[2], 0.f), fmaxf(Cbh[3] + Cbl[3], 0.f));
            }
        }
        {   // out = nf + h@uW2 + ub2
            #pragma unroll
            for (int np = 0; np < 4; np++) {
                float2 b0v = *(const float2*)(ub2s + np * 8 + 2 * m);
                float2 b1v = *(const float2*)(ub2s + (np + 4) * 8 + 2 * m);
                float C0h[4] = {b0v.x, b0v.y, b0v.x, b0v.y}, C0l[4] = {0,0,0,0};
                float C1h[4] = {b1v.x, b1v.y, b1v.x, b1v.y}, C1l[4] = {0,0,0,0};
                #pragma unroll
                for (int kc = 0; kc < 8; kc++) {
                    uint4 b0 = *(const uint4*)(smem + NOFF_BU2 + (((kc * 8 + np) * 32) + lane) * 16);
                    uint4 b1 = *(const uint4*)(smem + NOFF_BU2 + (((kc * 8 + np + 4) * 32) + lane) * 16);
                    mma2s(C0h, C0l, A2[kc], b0);
                    mma2s(C1h, C1l, A2[kc], b1);
                }
                float2 r00 = __ldg((const float2*)(nf + (size_t)n0 * 64 + np * 8 + 2 * m));
                float2 r10 = __ldg((const float2*)(nf + (size_t)n1 * 64 + np * 8 + 2 * m));
                float2 r01 = __ldg((const float2*)(nf + (size_t)n0 * 64 + (np + 4) * 8 + 2 * m));
                float2 r11 = __ldg((const float2*)(nf + (size_t)n1 * 64 + (np + 4) * 8 + 2 * m));
                *(float2*)(out_node + (size_t)n0 * 64 + np * 8 + 2 * m) =
                    make_float2(r00.x + C0h[0] + C0l[0], r00.y + C0h[1] + C0l[1]);
                *(float2*)(out_node + (size_t)n1 * 64 + np * 8 + 2 * m) =
                    make_float2(r10.x + C0h[2] + C0l[2], r10.y + C0h[3] + C0l[3]);
                *(float2*)(out_node + (size_t)n0 * 64 + (np + 4) * 8 + 2 * m) =
                    make_float2(r01.x + C1h[0] + C1l[0], r01.y + C1h[1] + C1l[1]);
                *(float2*)(out_node + (size_t)n1 * 64 + (np + 4) * 8 + 2 * m) =
                    make_float2(r11.x + C1h[2] + C1l[2], r11.y + C1h[3] + C1l[3]);
            }
        }
    }
}

// ---------------------------------------------------------------------------
// Edge kernel: 12 warps, 16 edges/warp-tile, SINGLE-PASS fp16 weights.
// B-fragments pack 2 adjacent nc per uint4 -> half the LDS bytes and MMAs.
// ---------------------------------------------------------------------------
__global__ __launch_bounds__(TPB_E, 1)
void edge_mlp_kernel(const float* __restrict__ ef,
                     const float* __restrict__ mW1, const float* __restrict__ mb1,
                     const float* __restrict__ mW2, const float* __restrict__ mb2,
                     const float* __restrict__ mW3, const float* __restrict__ mb3,
                     const int*   __restrict__ eidx,
                     float* __restrict__ agg)
{
    extern __shared__ char smem[];
    const int tid  = threadIdx.x;
    const int w    = tid >> 5;
    const int lane = tid & 31;
    const int m    = lane & 3;
    const int qrow = lane >> 2;

    STAGE_FRAGS1(OFF_W1, 2, 8, KR_W1E, mW1, 128, TPB_E)
    STAGE_FRAGS1(OFF_W2, 8, 8, KR_ID,  mW2, 128, TPB_E)
    STAGE_FRAGS1(OFF_W3, 8, 4, KR_ID,  mW3, 64,  TPB_E)
    float* b1s = (float*)(smem + OFF_B1);
    float* b2s = (float*)(smem + OFF_B2);
    float* b3s = (float*)(smem + OFF_B3);
    if (tid < 128) { b1s[tid] = mb1[tid]; b2s[tid] = mb2[tid]; }
    if (tid < 64)  { b3s[tid] = mb3[tid]; }
    __syncthreads();

    float* pq = (float*)(smem + OFF_SC) + w * (PQ_WARP_BYTES / 4);  // [16][PQ_STRIDE]
    const float4 bv1 = ((const float4*)b1s)[lane];

    const int gw = blockIdx.x * NW_E + w;
    const int gstride = gridDim.x * NW_E;

    for (int wt = gw; wt < N_WT_EDGE; wt += gstride) {
        const int base_e = wt * 16;

        int2 se = make_int2(0, 0);
        if (lane < 16) se = ((const int2*)eidx)[base_e + lane];
        __syncwarp();    // also fences pq/msg reuse from previous tile

        // ---- prefetch ef (K=32) ----
        const float* e0p = ef + (size_t)(base_e + qrow) * 32;
        const float* e1p = ef + (size_t)(base_e + qrow + 8) * 32;
        float2 v00 = __ldg((const float2*)(e0p + 2 * m));
        float2 v01 = __ldg((const float2*)(e0p + 2 * m + 8));
        float2 v02 = __ldg((const float2*)(e0p + 2 * m + 16));
        float2 v03 = __ldg((const float2*)(e0p + 2 * m + 24));
        float2 v10 = __ldg((const float2*)(e1p + 2 * m));
        float2 v11 = __ldg((const float2*)(e1p + 2 * m + 8));
        float2 v12 = __ldg((const float2*)(e1p + 2 * m + 16));
        float2 v13 = __ldg((const float2*)(e1p + 2 * m + 24));

        // ---- stage PQ = P[src] + Q[dst] + b1 into warp-private smem ----
        #pragma unroll 4
        for (int r = 0; r < 16; r++) {
            int sr = __shfl_sync(0xffffffffu, se.x, r);
            int dr = __shfl_sync(0xffffffffu, se.y, r);
            float4 pv = __ldg((const float4*)g_P + (size_t)sr * 32 + lane);
            float4 qv = __ldg((const float4*)g_Q + (size_t)dr * 32 + lane);
            float4 o;
            o.x = pv.x + qv.x + bv1.x; o.y = pv.y + qv.y + bv1.y;
            o.z = pv.z + qv.z + bv1.z; o.w = pv.w + qv.w + bv1.w;
            *(float4*)(pq + r * PQ_STRIDE + lane * 4) = o;
        }
        __syncwarp();

        // ---- A1 fragments (fp16) ----
        uint32_t A1[2][4];
        A1[0][0] = hpack2(v00.x, v00.y);
        A1[0][1] = hpack2(v10.x, v10.y);
        A1[0][2] = hpack2(v01.x, v01.y);
        A1[0][3] = hpack2(v11.x, v11.y);
        A1[1][0] = hpack2(v02.x, v02.y);
        A1[1][1] = hpack2(v12.x, v12.y);
        A1[1][2] = hpack2(v03.x, v03.y);
        A1[1][3] = hpack2(v13.x, v13.y);

        // ---- L1: C init = PQ; += ef@W1e (1 pass); -> A2 frags ----
        // chains: nc = 2j, 2j+1 (pair p=j) and 2j2, 2j2+1 (pair p=j2)
        uint32_t A2[8][4];
        #pragma unroll
        for (int j = 0; j < 4; j++) {
            int j2 = j + 4;
            float Ca[4], Cb[4], Cc[4], Cd[4];
            {
                float2 pa0 = *(const float2*)(pq + qrow * PQ_STRIDE + 16 * j + 2 * m);
                float2 pa1 = *(const float2*)(pq + (qrow + 8) * PQ_STRIDE + 16 * j + 2 * m);
                float2 pb0 = *(const float2*)(pq + qrow * PQ_STRIDE + 16 * j + 8 + 2 * m);
                float2 pb1 = *(const float2*)(pq + (qrow + 8) * PQ_STRIDE + 16 * j + 8 + 2 * m);
                float2 qa0 = *(const float2*)(pq + qrow * PQ_STRIDE + 16 * j2 + 2 * m);
                float2 qa1 = *(const float2*)(pq + (qrow + 8) * PQ_STRIDE + 16 * j2 + 2 * m);
                float2 qb0 = *(const float2*)(pq + qrow * PQ_STRIDE + 16 * j2 + 8 + 2 * m);
                float2 qb1 = *(const float2*)(pq + (qrow + 8) * PQ_STRIDE + 16 * j2 + 8 + 2 * m);
                Ca[0] = pa0.x; Ca[1] = pa0.y; Ca[2] = pa1.x; Ca[3] = pa1.y;
                Cb[0] = pb0.x; Cb[1] = pb0.y; Cb[2] = pb1.x; Cb[3] = pb1.y;
                Cc[0] = qa0.x; Cc[1] = qa0.y; Cc[2] = qa1.x; Cc[3] = qa1.y;
                Cd[0] = qb0.x; Cd[1] = qb0.y; Cd[2] = qb1.x; Cd[3] = qb1.y;
            }
            #pragma unroll
            for (int kc = 0; kc < 2; kc++) {
                uint4 u = *(const uint4*)(smem + OFF_W1 + (((kc * 8 + j) * 32) + lane) * 16);
                uint4 v = *(const uint4*)(smem + OFF_W1 + (((kc * 8 + j2) * 32) + lane) * 16);
                mma_f16(Ca, A1[kc], u.x, u.y);
                mma_f16(Cb, A1[kc], u.z, u.w);
                mma_f16(Cc, A1[kc], v.x, v.y);
                mma_f16(Cd, A1[kc], v.z, v.w);
            }
            A2[j][0]  = hpack2(fmaxf(Ca[0], 0.f), fmaxf(Ca[1], 0.f));
            A2[j][1]  = hpack2(fmaxf(Ca[2], 0.f), fmaxf(Ca[3], 0.f));
            A2[j][2]  = hpack2(fmaxf(Cb[0], 0.f), fmaxf(Cb[1], 0.f));
            A2[j][3]  = hpack2(fmaxf(Cb[2], 0.f), fmaxf(Cb[3], 0.f));
            A2[j2][0] = hpack2(fmaxf(Cc[0], 0.f), fmaxf(Cc[1], 0.f));
            A2[j2][1] = hpack2(fmaxf(Cc[2], 0.f), fmaxf(Cc[3], 0.f));
            A2[j2][2] = hpack2(fmaxf(Cd[0], 0.f), fmaxf(Cd[1], 0.f));
            A2[j2][3] = hpack2(fmaxf(Cd[2], 0.f), fmaxf(Cd[3], 0.f));
        }

        // ---- L2: C init = b2; += h1@W2 (1 pass); -> A3 frags ----
        uint32_t A3[8][4];
        #pragma unroll
        for (int j = 0; j < 4; j++) {
            int j2 = j + 4;
            float Ca[4], Cb[4], Cc[4], Cd[4];
            {
                float2 ba2 = *(const float2*)(b2s + (2 * j) * 8 + 2 * m);
                float2 bb2 = *(const float2*)(b2s + (2 * j + 1) * 8 + 2 * m);
                float2 bc2 = *(const float2*)(b2s + (2 * j2) * 8 + 2 * m);
                float2 bd2 = *(const float2*)(b2s + (2 * j2 + 1) * 8 + 2 * m);
                Ca[0] = ba2.x; Ca[1] = ba2.y; Ca[2] = ba2.x; Ca[3] = ba2.y;
                Cb[0] = bb2.x; Cb[1] = bb2.y; Cb[2] = bb2.x; Cb[3] = bb2.y;
                Cc[0] = bc2.x; Cc[1] = bc2.y; Cc[2] = bc2.x; Cc[3] = bc2.y;
                Cd[0] = bd2.x; Cd[1] = bd2.y; Cd[2] = bd2.x; Cd[3] = bd2.y;
            }
            #pragma unroll
            for (int kc = 0; kc < 8; kc++) {
                uint4 u = *(const uint4*)(smem + OFF_W2 + (((kc * 8 + j) * 32) + lane) * 16);
                uint4 v = *(const uint4*)(smem + OFF_W2 + (((kc * 8 + j2) * 32) + lane) * 16);
                mma_f16(Ca, A2[kc], u.x, u.y);
                mma_f16(Cb, A2[kc], u.z, u.w);
                mma_f16(Cc, A2[kc], v.x, v.y);
                mma_f16(Cd, A2[kc], v.z, v.w);
            }
            A3[j][0]  = hpack2(fmaxf(Ca[0], 0.f), fmaxf(Ca[1], 0.f));
            A3[j][1]  = hpack2(fmaxf(Ca[2], 0.f), fmaxf(Ca[3], 0.f));
            A3[j][2]  = hpack2(fmaxf(Cb[0], 0.f), fmaxf(Cb[1], 0.f));
            A3[j][3]  = hpack2(fmaxf(Cb[2], 0.f), fmaxf(Cb[3], 0.f));
            A3[j2][0] = hpack2(fmaxf(Cc[0], 0.f), fmaxf(Cc[1], 0.f));
            A3[j2][1] = hpack2(fmaxf(Cc[2], 0.f), fmaxf(Cc[3], 0.f));
            A3[j2][2] = hpack2(fmaxf(Cd[0], 0.f), fmaxf(Cd[1], 0.f));
            A3[j2][3] = hpack2(fmaxf(Cd[2], 0.f), fmaxf(Cd[3], 0.f));
        }

        // ---- L3: C init = b3; += h2@W3 (1 pass); -> msg ----
        // pairs p = 2t, 2t+1 -> nc = 4t .. 4t+3
        float* msg = pq;
        __syncwarp();   // pq reads (L1 init) complete before msg overwrite
        #pragma unroll
        for (int t = 0; t < 2; t++) {
            int p0 = 2 * t, p1 = 2 * t + 1;
            float Ca[4], Cb[4], Cc[4], Cd[4];
            {
                float2 b0v = *(const float2*)(b3s + (4 * t) * 8 + 2 * m);
                float2 b1v = *(const float2*)(b3s + (4 * t + 1) * 8 + 2 * m);
                float2 b2v = *(const float2*)(b3s + (4 * t + 2) * 8 + 2 * m);
                float2 b3v = *(const float2*)(b3s + (4 * t + 3) * 8 + 2 * m);
                Ca[0] = b0v.x; Ca[1] = b0v.y; Ca[2] = b0v.x; Ca[3] = b0v.y;
                Cb[0] = b1v.x; Cb[1] = b1v.y; Cb[2] = b1v.x; Cb[3] = b1v.y;
                Cc[0] = b2v.x; Cc[1] = b2v.y; Cc[2] = b2v.x; Cc[3] = b2v.y;
                Cd[0] = b3v.x; Cd[1] = b3v.y; Cd[2] = b3v.x; Cd[3] = b3v.y;
            }
            #pragma unroll
            for (int kc = 0; kc < 8; kc++) {
                uint4 u = *(const uint4*)(smem + OFF_W3 + (((kc * 4 + p0) * 32) + lane) * 16);
                uint4 v = *(const uint4*)(smem + OFF_W3 + (((kc * 4 + p1) * 32) + lane) * 16);
                mma_f16(Ca, A3[kc], u.x, u.y);
                mma_f16(Cb, A3[kc], u.z, u.w);
                mma_f16(Cc, A3[kc], v.x, v.y);
                mma_f16(Cd, A3[kc], v.z, v.w);
            }
            *(float2*)(msg + qrow * MSG_STRIDE + 8 * (4 * t) + 2 * m) = make_float2(Ca[0], Ca[1]);
            *(float2*)(msg + (qrow + 8) * MSG_STRIDE + 8 * (4 * t) + 2 * m) = make_float2(Ca[2], Ca[3]);
            *(float2*)(msg + qrow * MSG_STRIDE + 8 * (4 * t + 1) + 2 * m) = make_float2(Cb[0], Cb[1]);
            *(float2*)(msg + (qrow + 8) * MSG_STRIDE + 8 * (4 * t + 1) + 2 * m) = make_float2(Cb[2], Cb[3]);
            *(float2*)(msg + qrow * MSG_STRIDE + 8 * (4 * t + 2) + 2 * m) = make_float2(Cc[0], Cc[1]);
            *(float2*)(msg + (qrow + 8) * MSG_STRIDE + 8 * (4 * t + 2) + 2 * m) = make_float2(Cc[2], Cc[3]);
            *(float2*)(msg + qrow * MSG_STRIDE + 8 * (4 * t + 3) + 2 * m) = make_float2(Cd[0], Cd[1]);
            *(float2*)(msg + (qrow + 8) * MSG_STRIDE + 8 * (4 * t + 3) + 2 * m) = make_float2(Cd[2], Cd[3]);
        }
        __syncwarp();

        // ---- scatter: 16 edges x 16 float4 atomics ----
        #pragma unroll
        for (int it = 0; it < 8; it++) {
            int slot = it * 32 + lane;
            int e = slot >> 4, q = slot & 15;
            float4 v = *(const float4*)(msg + e * MSG_STRIDE + q * 4);
            int dn = __shfl_sync(0xffffffffu, se.y, e);
            atomicAdd(((float4*)(agg + (size_t)dn * 64)) + q, v);
        }
    }
}

extern "C" void kernel_launch(void* const* d_in, const int* in_sizes, int n_in,
                              void* d_out, int out_size)
{
    const float* nf  = (const float*)d_in[0];
    const float* ef  = (const float*)d_in[1];
    const float* stx = (const float*)d_in[2];
    const float* mW1 = (const float*)d_in[3];
    const float* mb1 = (const float*)d_in[4];
    const float* mW2 = (const float*)d_in[5];
    const float* mb2 = (const float*)d_in[6];
    const float* mW3 = (const float*)d_in[7];
    const float* mb3 = (const float*)d_in[8];
    const float* uW1 = (const float*)d_in[9];
    const float* ub1 = (const float*)d_in[10];
    const float* uW2 = (const float*)d_in[11];
    const float* ub2 = (const float*)d_in[12];
    const int*  eidx = (const int*)d_in[13];

    float* out_node = (float*)d_out;
    float* agg      = out_node + (size_t)N_NODES_C * 64;

    cudaFuncSetAttribute(edge_mlp_kernel,
                         cudaFuncAttributeMaxDynamicSharedMemorySize, EDGE_SMEM_BYTES);
    cudaFuncSetAttribute(node_fused_kernel,
                         cudaFuncAttributeMaxDynamicSharedMemorySize, NODEF_SMEM_BYTES);

    int dev = 0;
    cudaGetDevice(&dev);
    int sms = 148;
    cudaDeviceGetAttribute(&sms, cudaDevAttrMultiProcessorCount, dev);

    node_fused_kernel<<<sms, TPB_N, NODEF_SMEM_BYTES>>>(nf, stx, mW1, uW1, ub1, uW2, ub2,
                                                        out_node, agg);
    edge_mlp_kernel<<<sms, TPB_E, EDGE_SMEM_BYTES>>>(ef, mW1, mb1, mW2, mb2,
                                                     mW3, mb3, eidx, agg);
}

// round 15
// speedup vs baseline: 1.6857x; 1.1547x over previous
#include <cuda_runtime.h>
#include <cuda_fp16.h>
#include <cstdint>

#define N_NODES_C 50000
#define N_EDGES_C 800000

#define TPB_N 256          // node kernel: 8 warps
#define TPB_E 384          // edge kernel: 12 warps
#define NW_E 12
#define N_WT_EDGE (N_EDGES_C / 16)          // 50000 warp-tiles
#define N_WT_NODE (N_NODES_C / 16)          // 3125 warp-tiles

// Per-node layer-1 partials, fp16x2-packed (cols 2c,2c+1 per uint32; 64 u32/row)
__device__ uint32_t g_Ph[(size_t)N_NODES_C * 64];
__device__ uint32_t g_Qh[(size_t)N_NODES_C * 64];

// ---------------- edge kernel SMEM (bytes): 1-pass fp16, nc-pair packed ----
#define OFF_W1 0                          // kc=2, ncp=8 : 8192
#define OFF_W2 8192                       // kc=8, ncp=8 : 32768
#define OFF_W3 40960                      // kc=8, ncp=4 : 16384
#define OFF_B1 57344                      // 128 f32
#define OFF_B2 57856                      // 128 f32
#define OFF_B3 58368                      // 64 f32
#define OFF_SC 58624                      // 12 warps * 1152 f32
#define PQ_STRIDE_U32 68                  // 64 u32 data + 4 pad (mod 32 == 4)
#define MSG_STRIDE 72
#define SC_WARP_FLOATS 1152               // pq 16x68 u32 (1088) fits; msg 16x72 f32
#define EDGE_SMEM_BYTES (OFF_SC + NW_E*SC_WARP_FLOATS*4)   // 113920

// ---------------- fused node kernel SMEM (bytes): 2-pass (accuracy) --------
#define NOFF_BP  0
#define NOFF_BQ  49152
#define NOFF_BU1 81920
#define NOFF_BU2 131072
#define NOFF_UB1 163840
#define NOFF_UB2 164352
#define NODEF_SMEM_BYTES (164608)

// pack two floats into fp16x2 (low half = first arg)
static __device__ __forceinline__ uint32_t hpack2(float x0, float x1) {
    uint32_t r;
    asm("cvt.rn.f16x2.f32 %0, %1, %2;" : "=r"(r) : "f"(x1), "f"(x0));
    return r;
}
static __device__ __forceinline__ float2 hunpack2(uint32_t v) {
    __half2 h = *reinterpret_cast<__half2*>(&v);
    return __half22float2(h);
}
// fp16 split of a float pair -> hi fp16x2 + residual-lo fp16x2
static __device__ __forceinline__ void hsplit2(float x0, float x1,
                                               uint32_t& hi, uint32_t& lo) {
    uint32_t h = hpack2(x0, x1);
    __half2 hh = *reinterpret_cast<__half2*>(&h);
    float r0 = x0 - __half2float(__low2half(hh));
    float r1 = x1 - __half2float(__high2half(hh));
    lo = hpack2(r0, r1);
    hi = h;
}

// D += A(16x16 fp16) * B(16x8 fp16), fp32 accum
static __device__ __forceinline__ void mma_f16(float* d, const uint32_t* a,
                                               uint32_t b0, uint32_t b1) {
    asm volatile("mma.sync.aligned.m16n8k16.row.col.f32.f16.f16.f32 "
        "{%0,%1,%2,%3}, {%4,%5,%6,%7}, {%8,%9}, {%0,%1,%2,%3};"
        : "+f"(d[0]), "+f"(d[1]), "+f"(d[2]), "+f"(d[3])
        : "r"(a[0]), "r"(a[1]), "r"(a[2]), "r"(a[3]), "r"(b0), "r"(b1));
}
// 2-pass weight-split MMA (node kernel): Ch += A*Bh ; Cl += A*Bl
static __device__ __forceinline__ void mma2s(float* Ch, float* Cl,
                                             const uint32_t* a, uint4 bw) {
    mma_f16(Ch, a, bw.x, bw.y);
    mma_f16(Cl, a, bw.z, bw.w);
}

// 2-pass fragment staging (node kernel): uint4 = {b0h,b1h,b0l,b1l} per nc
#define STAGE_FRAGS2(dst_off, KC, NC, KROW_EXPR, SRC_PTR, SRC_N, STRIDE)        \
    for (int idx = tid; idx < (KC) * (NC) * 32; idx += (STRIDE)) {              \
        int T = idx & 31, nc = (idx >> 5) % (NC), kc = idx / ((NC) * 32);       \
        int n = nc * 8 + (T >> 2);                                              \
        int k0 = kc * 16 + (T & 3) * 2;                                         \
        int ka = (KROW_EXPR(k0)), kb = (KROW_EXPR(k0 + 1));                     \
        int kd = (KROW_EXPR(k0 + 8)), ke = (KROW_EXPR(k0 + 9));                 \
        float w00 = (SRC_PTR)[ka * (SRC_N) + n], w01 = (SRC_PTR)[kb * (SRC_N) + n]; \
        float w10 = (SRC_PTR)[kd * (SRC_N) + n], w11 = (SRC_PTR)[ke * (SRC_N) + n]; \
        uint32_t b0h, b0l, b1h, b1l;                                            \
        hsplit2(w00, w01, b0h, b0l);                                            \
        hsplit2(w10, w11, b1h, b1l);                                            \
        *(uint4*)(smem + (dst_off) + idx * 16) = make_uint4(b0h, b1h, b0l, b1l); \
    }

// 1-pass fragment staging (edge kernel): uint4 packs TWO adjacent nc
#define STAGE_FRAGS1(dst_off, KC, NCP, KROW_EXPR, SRC_PTR, SRC_N, STRIDE)       \
    for (int idx = tid; idx < (KC) * (NCP) * 32; idx += (STRIDE)) {             \
        int T = idx & 31, p = (idx >> 5) % (NCP), kc = idx / ((NCP) * 32);      \
        int n0 = (2 * p) * 8 + (T >> 2);                                        \
        int n1 = n0 + 8;                                                        \
        int k0 = kc * 16 + (T & 3) * 2;                                         \
        int ka = (KROW_EXPR(k0)), kb = (KROW_EXPR(k0 + 1));                     \
        int kd = (KROW_EXPR(k0 + 8)), ke = (KROW_EXPR(k0 + 9));                 \
        uint32_t a0 = hpack2((SRC_PTR)[ka * (SRC_N) + n0], (SRC_PTR)[kb * (SRC_N) + n0]); \
        uint32_t a1 = hpack2((SRC_PTR)[kd * (SRC_N) + n0], (SRC_PTR)[ke * (SRC_N) + n0]); \
        uint32_t c0 = hpack2((SRC_PTR)[ka * (SRC_N) + n1], (SRC_PTR)[kb * (SRC_N) + n1]); \
        uint32_t c1 = hpack2((SRC_PTR)[kd * (SRC_N) + n1], (SRC_PTR)[ke * (SRC_N) + n1]); \
        *(uint4*)(smem + (dst_off) + idx * 16) = make_uint4(a0, a1, c0, c1);    \
    }

#define KR_ID(k)    (k)
#define KR_W1E(k)   (128 + (k))
#define KR_P(k)     ((k) < 64 ? (k) : (k) + 96)
#define KR_Q(k)     (64 + (k))

// ---------------------------------------------------------------------------
// Fused node kernel (R13 + fp16x2-packed P/Q stores)
// ---------------------------------------------------------------------------
__global__ __launch_bounds__(TPB_N, 1)
void node_fused_kernel(const float* __restrict__ nf,
                       const float* __restrict__ stx,
                       const float* __restrict__ mW1,
                       const float* __restrict__ uW1, const float* __restrict__ ub1,
                       const float* __restrict__ uW2, const float* __restrict__ ub2,
                       float* __restrict__ out_node,
                       float* __restrict__ agg)
{
    extern __shared__ char smem[];
    const int tid  = threadIdx.x;
    const int w    = tid >> 5;
    const int lane = tid & 31;
    const int m    = lane & 3;
    const int qrow = lane >> 2;

    STAGE_FRAGS2(NOFF_BP,  6, 16, KR_P,  mW1, 128, TPB_N)
    STAGE_FRAGS2(NOFF_BQ,  4, 16, KR_Q,  mW1, 128, TPB_N)
    STAGE_FRAGS2(NOFF_BU1, 6, 16, KR_ID, uW1, 128, TPB_N)
    STAGE_FRAGS2(NOFF_BU2, 8, 8,  KR_ID, uW2, 64,  TPB_N)
    float* ub1s = (float*)(smem + NOFF_UB1);
    float* ub2s = (float*)(smem + NOFF_UB2);
    if (tid < 128) ub1s[tid] = ub1[tid];
    if (tid < 64)  ub2s[tid] = ub2[tid];
    __syncthreads();

    const int gw = blockIdx.x * 8 + w;
    const int gstride = gridDim.x * 8;
    const float4 z4 = make_float4(0.f, 0.f, 0.f, 0.f);

    for (int wt = gw; wt < N_WT_NODE; wt += gstride) {
        const int n0 = wt * 16 + qrow;
        const int n1 = n0 + 8;

        #pragma unroll
        for (int s = lane; s < 256; s += 32) {
            int r = s >> 4, q = s & 15;
            *(float4*)(agg + (size_t)(wt * 16 + r) * 64 + q * 4) = z4;
        }

        uint32_t xA[6][4];
        #pragma unroll
        for (int kc = 0; kc < 4; kc++) {
            float2 v0  = __ldg((const float2*)(nf + (size_t)n0 * 64 + kc * 16 + 2 * m));
            float2 v1  = __ldg((const float2*)(nf + (size_t)n1 * 64 + kc * 16 + 2 * m));
            float2 v0b = __ldg((const float2*)(nf + (size_t)n0 * 64 + kc * 16 + 8 + 2 * m));
            float2 v1b = __ldg((const float2*)(nf + (size_t)n1 * 64 + kc * 16 + 8 + 2 * m));
            xA[kc][0] = hpack2(v0.x, v0.y);
            xA[kc][1] = hpack2(v1.x, v1.y);
            xA[kc][2] = hpack2(v0b.x, v0b.y);
            xA[kc][3] = hpack2(v1b.x, v1b.y);
        }
        #pragma unroll
        for (int kc = 4; kc < 6; kc++) {
            int c = (kc - 4) * 16;
            float2 v0  = __ldg((const float2*)(stx + (size_t)n0 * 32 + c + 2 * m));
            float2 v1  = __ldg((const float2*)(stx + (size_t)n1 * 32 + c + 2 * m));
            float2 v0b = __ldg((const float2*)(stx + (size_t)n0 * 32 + c + 8 + 2 * m));
            float2 v1b = __ldg((const float2*)(stx + (size_t)n1 * 32 + c + 8 + 2 * m));
            xA[kc][0] = hpack2(v0.x, v0.y);
            xA[kc][1] = hpack2(v1.x, v1.y);
            xA[kc][2] = hpack2(v0b.x, v0b.y);
            xA[kc][3] = hpack2(v1b.x, v1b.y);
        }

        {   // P (K=96) -> fp16x2 packed
            #pragma unroll
            for (int np = 0; np < 8; np++) {
                float C0h[4] = {0,0,0,0}, C0l[4] = {0,0,0,0};
                float C1h[4] = {0,0,0,0}, C1l[4] = {0,0,0,0};
                #pragma unroll
                for (int kc = 0; kc < 6; kc++) {
                    uint4 b0 = *(const uint4*)(smem + NOFF_BP + (((kc * 16 + np) * 32) + lane) * 16);
                    uint4 b1 = *(const uint4*)(smem + NOFF_BP + (((kc * 16 + np + 8) * 32) + lane) * 16);
                    mma2s(C0h, C0l, xA[kc], b0);
                    mma2s(C1h, C1l, xA[kc], b1);
                }
                g_Ph[(size_t)n0 * 64 + np * 4 + m] = hpack2(C0h[0] + C0l[0], C0h[1] + C0l[1]);
                g_Ph[(size_t)n1 * 64 + np * 4 + m] = hpack2(C0h[2] + C0l[2], C0h[3] + C0l[3]);
                g_Ph[(size_t)n0 * 64 + (np + 8) * 4 + m] = hpack2(C1h[0] + C1l[0], C1h[1] + C1l[1]);
                g_Ph[(size_t)n1 * 64 + (np + 8) * 4 + m] = hpack2(C1h[2] + C1l[2], C1h[3] + C1l[3]);
            }
        }
        {   // Q (K=64) -> fp16x2 packed
            #pragma unroll
            for (int np = 0; np < 8; np++) {
                float C0h[4] = {0,0,0,0}, C0l[4] = {0,0,0,0};
                float C1h[4] = {0,0,0,0}, C1l[4] = {0,0,0,0};
                #pragma unroll
                for (int kc = 0; kc < 4; kc++) {
                    uint4 b0 = *(const uint4*)(smem + NOFF_BQ + (((kc * 16 + np) * 32) + lane) * 16);
                    uint4 b1 = *(const uint4*)(smem + NOFF_BQ + (((kc * 16 + np + 8) * 32) + lane) * 16);
                    mma2s(C0h, C0l, xA[kc], b0);
                    mma2s(C1h, C1l, xA[kc], b1);
                }
                g_Qh[(size_t)n0 * 64 + np * 4 + m] = hpack2(C0h[0] + C0l[0], C0h[1] + C0l[1]);
                g_Qh[(size_t)n1 * 64 + np * 4 + m] = hpack2(C0h[2] + C0l[2], C0h[3] + C0l[3]);
                g_Qh[(size_t)n0 * 64 + (np + 8) * 4 + m] = hpack2(C1h[0] + C1l[0], C1h[1] + C1l[1]);
                g_Qh[(size_t)n1 * 64 + (np + 8) * 4 + m] = hpack2(C1h[2] + C1l[2], C1h[3] + C1l[3]);
            }
        }
        uint32_t A2[8][4];
        {   // h = relu(x@uW1 + ub1)
            #pragma unroll
            for (int j = 0; j < 8; j++) {
                float2 ba = *(const float2*)(ub1s + (2 * j) * 8 + 2 * m);
                float2 bb = *(const float2*)(ub1s + (2 * j + 1) * 8 + 2 * m);
                float Cah[4] = {ba.x, ba.y, ba.x, ba.y}, Cal[4] = {0,0,0,0};
                float Cbh[4] = {bb.x, bb.y, bb.x, bb.y}, Cbl[4] = {0,0,0,0};
                #pragma unroll
                for (int kc = 0; kc < 6; kc++) {
                    uint4 ba4 = *(const uint4*)(smem + NOFF_BU1 + (((kc * 16 + 2 * j) * 32) + lane) * 16);
                    uint4 bb4 = *(const uint4*)(smem + NOFF_BU1 + (((kc * 16 + 2 * j + 1) * 32) + lane) * 16);
                    mma2s(Cah, Cal, xA[kc], ba4);
                    mma2s(Cbh, Cbl, xA[kc], bb4);
                }
                A2[j][0] = hpack2(fmaxf(Cah[0] + Cal[0], 0.f), fmaxf(Cah[1] + Cal[1], 0.f));
                A2[j][1] = hpack2(fmaxf(Cah[2] + Cal[2], 0.f), fmaxf(Cah[3] + Cal[3], 0.f));
                A2[j][2] = hpack2(fmaxf(Cbh[0] + Cbl[0], 0.f), fmaxf(Cbh[1] + Cbl[1], 0.f));
                A2[j][3] = hpack2(fmaxf(Cbh[2] + Cbl[2], 0.f), fmaxf(Cbh[3] + Cbl[3], 0.f));
            }
        }
        {   // out = nf + h@uW2 + ub2
            #pragma unroll
            for (int np = 0; np < 4; np++) {
                float2 b0v = *(const float2*)(ub2s + np * 8 + 2 * m);
                float2 b1v = *(const float2*)(ub2s + (np + 4) * 8 + 2 * m);
                float C0h[4] = {b0v.x, b0v.y, b0v.x, b0v.y}, C0l[4] = {0,0,0,0};
                float C1h[4] = {b1v.x, b1v.y, b1v.x, b1v.y}, C1l[4] = {0,0,0,0};
                #pragma unroll
                for (int kc = 0; kc < 8; kc++) {
                    uint4 b0 = *(const uint4*)(smem + NOFF_BU2 + (((kc * 8 + np) * 32) + lane) * 16);
                    uint4 b1 = *(const uint4*)(smem + NOFF_BU2 + (((kc * 8 + np + 4) * 32) + lane) * 16);
                    mma2s(C0h, C0l, A2[kc], b0);
                    mma2s(C1h, C1l, A2[kc], b1);
                }
                float2 r00 = __ldg((const float2*)(nf + (size_t)n0 * 64 + np * 8 + 2 * m));
                float2 r10 = __ldg((const float2*)(nf + (size_t)n1 * 64 + np * 8 + 2 * m));
                float2 r01 = __ldg((const float2*)(nf + (size_t)n0 * 64 + (np + 4) * 8 + 2 * m));
                float2 r11 = __ldg((const float2*)(nf + (size_t)n1 * 64 + (np + 4) * 8 + 2 * m));
                *(float2*)(out_node + (size_t)n0 * 64 + np * 8 + 2 * m) =
                    make_float2(r00.x + C0h[0] + C0l[0], r00.y + C0h[1] + C0l[1]);
                *(float2*)(out_node + (size_t)n1 * 64 + np * 8 + 2 * m) =
                    make_float2(r10.x + C0h[2] + C0l[2], r10.y + C0h[3] + C0l[3]);
                *(float2*)(out_node + (size_t)n0 * 64 + (np + 4) * 8 + 2 * m) =
                    make_float2(r01.x + C1h[0] + C1l[0], r01.y + C1h[1] + C1l[1]);
                *(float2*)(out_node + (size_t)n1 * 64 + (np + 4) * 8 + 2 * m) =
                    make_float2(r11.x + C1h[2] + C1l[2], r11.y + C1h[3] + C1l[3]);
            }
        }
    }
}

// ---------------------------------------------------------------------------
// Edge kernel: 12 warps, 1-pass fp16 weights, fp16 PQ gather + staging.
// ---------------------------------------------------------------------------
__global__ __launch_bounds__(TPB_E, 1)
void edge_mlp_kernel(const float* __restrict__ ef,
                     const float* __restrict__ mW1, const float* __restrict__ mb1,
                     const float* __restrict__ mW2, const float* __restrict__ mb2,
                     const float* __restrict__ mW3, const float* __restrict__ mb3,
                     const int*   __restrict__ eidx,
                     float* __restrict__ agg)
{
    extern __shared__ char smem[];
    const int tid  = threadIdx.x;
    const int w    = tid >> 5;
    const int lane = tid & 31;
    const int m    = lane & 3;
    const int qrow = lane >> 2;

    STAGE_FRAGS1(OFF_W1, 2, 8, KR_W1E, mW1, 128, TPB_E)
    STAGE_FRAGS1(OFF_W2, 8, 8, KR_ID,  mW2, 128, TPB_E)
    STAGE_FRAGS1(OFF_W3, 8, 4, KR_ID,  mW3, 64,  TPB_E)
    float* b1s = (float*)(smem + OFF_B1);
    float* b2s = (float*)(smem + OFF_B2);
    float* b3s = (float*)(smem + OFF_B3);
    if (tid < 128) { b1s[tid] = mb1[tid]; b2s[tid] = mb2[tid]; }
    if (tid < 64)  { b3s[tid] = mb3[tid]; }
    __syncthreads();

    float*     msg  = (float*)(smem + OFF_SC) + w * SC_WARP_FLOATS;   // [16][72] f32
    uint32_t*  pq16 = (uint32_t*)msg;                                 // [16][68] u32 (fp16x2)
    const float4 bv1 = ((const float4*)b1s)[lane];                    // b1 cols 4l..4l+3

    const int gw = blockIdx.x * NW_E + w;
    const int gstride = gridDim.x * NW_E;

    for (int wt = gw; wt < N_WT_EDGE; wt += gstride) {
        const int base_e = wt * 16;

        int2 se = make_int2(0, 0);
        if (lane < 16) se = ((const int2*)eidx)[base_e + lane];
        __syncwarp();    // scratch reuse fence from previous tile

        // ---- prefetch ef (K=32) ----
        const float* e0p = ef + (size_t)(base_e + qrow) * 32;
        const float* e1p = ef + (size_t)(base_e + qrow + 8) * 32;
        float2 v00 = __ldg((const float2*)(e0p + 2 * m));
        float2 v01 = __ldg((const float2*)(e0p + 2 * m + 8));
        float2 v02 = __ldg((const float2*)(e0p + 2 * m + 16));
        float2 v03 = __ldg((const float2*)(e0p + 2 * m + 24));
        float2 v10 = __ldg((const float2*)(e1p + 2 * m));
        float2 v11 = __ldg((const float2*)(e1p + 2 * m + 8));
        float2 v12 = __ldg((const float2*)(e1p + 2 * m + 16));
        float2 v13 = __ldg((const float2*)(e1p + 2 * m + 24));

        // ---- stage PQ = fp16(P[src] + Q[dst] + b1) into warp smem ----
        // lane covers cols 4l..4l+3 (uint2 = 2 fp16x2), row stride 68 u32
        #pragma unroll 4
        for (int r = 0; r < 16; r++) {
            int sr = __shfl_sync(0xffffffffu, se.x, r);
            int dr = __shfl_sync(0xffffffffu, se.y, r);
            uint2 pv = __ldg((const uint2*)g_Ph + (size_t)sr * 32 + lane);
            uint2 qv = __ldg((const uint2*)g_Qh + (size_t)dr * 32 + lane);
            float2 p0 = hunpack2(pv.x), p1 = hunpack2(pv.y);
            float2 q0 = hunpack2(qv.x), q1 = hunpack2(qv.y);
            uint2 o;
            o.x = hpack2(p0.x + q0.x + bv1.x, p0.y + q0.y + bv1.y);
            o.y = hpack2(p1.x + q1.x + bv1.z, p1.y + q1.y + bv1.w);
            *(uint2*)(pq16 + r * PQ_STRIDE_U32 + 2 * lane) = o;
        }
        __syncwarp();

        // ---- A1 fragments (fp16) ----
        uint32_t A1[2][4];
        A1[0][0] = hpack2(v00.x, v00.y);
        A1[0][1] = hpack2(v10.x, v10.y);
        A1[0][2] = hpack2(v01.x, v01.y);
        A1[0][3] = hpack2(v11.x, v11.y);
        A1[1][0] = hpack2(v02.x, v02.y);
        A1[1][1] = hpack2(v12.x, v12.y);
        A1[1][2] = hpack2(v03.x, v03.y);
        A1[1][3] = hpack2(v13.x, v13.y);

        // ---- L1: C init = PQ (fp16->fp32); += ef@W1e (1 pass); -> A2 ----
        uint32_t A2[8][4];
        #pragma unroll
        for (int j = 0; j < 4; j++) {
            int j2 = j + 4;
            float Ca[4], Cb[4], Cc[4], Cd[4];
            {
                // fragment (row, cols 16j+2m..+1) = u32 idx 8j+m
                float2 a0 = hunpack2(pq16[qrow * PQ_STRIDE_U32 + 8 * j + m]);
                float2 a1 = hunpack2(pq16[(qrow + 8) * PQ_STRIDE_U32 + 8 * j + m]);
                float2 b0 = hunpack2(pq16[qrow * PQ_STRIDE_U32 + 8 * j + 4 + m]);
                float2 b1 = hunpack2(pq16[(qrow + 8) * PQ_STRIDE_U32 + 8 * j + 4 + m]);
                float2 c0 = hunpack2(pq16[qrow * PQ_STRIDE_U32 + 8 * j2 + m]);
                float2 c1 = hunpack2(pq16[(qrow + 8) * PQ_STRIDE_U32 + 8 * j2 + m]);
                float2 d0 = hunpack2(pq16[qrow * PQ_STRIDE_U32 + 8 * j2 + 4 + m]);
                float2 d1 = hunpack2(pq16[(qrow + 8) * PQ_STRIDE_U32 + 8 * j2 + 4 + m]);
                Ca[0] = a0.x; Ca[1] = a0.y; Ca[2] = a1.x; Ca[3] = a1.y;
                Cb[0] = b0.x; Cb[1] = b0.y; Cb[2] = b1.x; Cb[3] = b1.y;
                Cc[0] = c0.x; Cc[1] = c0.y; Cc[2] = c1.x; Cc[3] = c1.y;
                Cd[0] = d0.x; Cd[1] = d0.y; Cd[2] = d1.x; Cd[3] = d1.y;
            }
            #pragma unroll
            for (int kc = 0; kc < 2; kc++) {
                uint4 u = *(const uint4*)(smem + OFF_W1 + (((kc * 8 + j) * 32) + lane) * 16);
                uint4 v = *(const uint4*)(smem + OFF_W1 + (((kc * 8 + j2) * 32) + lane) * 16);
                mma_f16(Ca, A1[kc], u.x, u.y);
                mma_f16(Cb, A1[kc], u.z, u.w);
                mma_f16(Cc, A1[kc], v.x, v.y);
                mma_f16(Cd, A1[kc], v.z, v.w);
            }
            A2[j][0]  = hpack2(fmaxf(Ca[0], 0.f), fmaxf(Ca[1], 0.f));
            A2[j][1]  = hpack2(fmaxf(Ca[2], 0.f), fmaxf(Ca[3], 0.f));
            A2[j][2]  = hpack2(fmaxf(Cb[0], 0.f), fmaxf(Cb[1], 0.f));
            A2[j][3]  = hpack2(fmaxf(Cb[2], 0.f), fmaxf(Cb[3], 0.f));
            A2[j2][0] = hpack2(fmaxf(Cc[0], 0.f), fmaxf(Cc[1], 0.f));
            A2[j2][1] = hpack2(fmaxf(Cc[2], 0.f), fmaxf(Cc[3], 0.f));
            A2[j2][2] = hpack2(fmaxf(Cd[0], 0.f), fmaxf(Cd[1], 0.f));
            A2[j2][3] = hpack2(fmaxf(Cd[2], 0.f), fmaxf(Cd[3], 0.f));
        }

        // ---- L2: C init = b2; += h1@W2 (1 pass); -> A3 ----
        uint32_t A3[8][4];
        #pragma unroll
        for (int j = 0; j < 4; j++) {
            int j2 = j + 4;
            float Ca[4], Cb[4], Cc[4], Cd[4];
            {
                float2 ba2 = *(const float2*)(b2s + (2 * j) * 8 + 2 * m);
                float2 bb2 = *(const float2*)(b2s + (2 * j + 1) * 8 + 2 * m);
                float2 bc2 = *(const float2*)(b2s + (2 * j2) * 8 + 2 * m);
                float2 bd2 = *(const float2*)(b2s + (2 * j2 + 1) * 8 + 2 * m);
                Ca[0] = ba2.x; Ca[1] = ba2.y; Ca[2] = ba2.x; Ca[3] = ba2.y;
                Cb[0] = bb2.x; Cb[1] = bb2.y; Cb[2] = bb2.x; Cb[3] = bb2.y;
                Cc[0] = bc2.x; Cc[1] = bc2.y; Cc[2] = bc2.x; Cc[3] = bc2.y;
                Cd[0] = bd2.x; Cd[1] = bd2.y; Cd[2] = bd2.x; Cd[3] = bd2.y;
            }
            #pragma unroll
            for (int kc = 0; kc < 8; kc++) {
                uint4 u = *(const uint4*)(smem + OFF_W2 + (((kc * 8 + j) * 32) + lane) * 16);
                uint4 v = *(const uint4*)(smem + OFF_W2 + (((kc * 8 + j2) * 32) + lane) * 16);
                mma_f16(Ca, A2[kc], u.x, u.y);
                mma_f16(Cb, A2[kc], u.z, u.w);
                mma_f16(Cc, A2[kc], v.x, v.y);
                mma_f16(Cd, A2[kc], v.z, v.w);
            }
            A3[j][0]  = hpack2(fmaxf(Ca[0], 0.f), fmaxf(Ca[1], 0.f));
            A3[j][1]  = hpack2(fmaxf(Ca[2], 0.f), fmaxf(Ca[3], 0.f));
            A3[j][2]  = hpack2(fmaxf(Cb[0], 0.f), fmaxf(Cb[1], 0.f));
            A3[j][3]  = hpack2(fmaxf(Cb[2], 0.f), fmaxf(Cb[3], 0.f));
            A3[j2][0] = hpack2(fmaxf(Cc[0], 0.f), fmaxf(Cc[1], 0.f));
            A3[j2][1] = hpack2(fmaxf(Cc[2], 0.f), fmaxf(Cc[3], 0.f));
            A3[j2][2] = hpack2(fmaxf(Cd[0], 0.f), fmaxf(Cd[1], 0.f));
            A3[j2][3] = hpack2(fmaxf(Cd[2], 0.f), fmaxf(Cd[3], 0.f));
        }

        // ---- L3: C init = b3; += h2@W3 (1 pass); -> msg ----
        __syncwarp();   // pq16 reads (L1 init) complete before msg overwrite
        #pragma unroll
        for (int t = 0; t < 2; t++) {
            int p0 = 2 * t, p1 = 2 * t + 1;
            float Ca[4], Cb[4], Cc[4], Cd[4];
            {
                float2 b0v = *(const float2*)(b3s + (4 * t) * 8 + 2 * m);
                float2 b1v = *(const float2*)(b3s + (4 * t + 1) * 8 + 2 * m);
                float2 b2v = *(const float2*)(b3s + (4 * t + 2) * 8 + 2 * m);
                float2 b3v = *(const float2*)(b3s + (4 * t + 3) * 8 + 2 * m);
                Ca[0] = b0v.x; Ca[1] = b0v.y; Ca[2] = b0v.x; Ca[3] = b0v.y;
                Cb[0] = b1v.x; Cb[1] = b1v.y; Cb[2] = b1v.x; Cb[3] = b1v.y;
                Cc[0] = b2v.x; Cc[1] = b2v.y; Cc[2] = b2v.x; Cc[3] = b2v.y;
                Cd[0] = b3v.x; Cd[1] = b3v.y; Cd[2] = b3v.x; Cd[3] = b3v.y;
            }
            #pragma unroll
            for (int kc = 0; kc < 8; kc++) {
                uint4 u = *(const uint4*)(smem + OFF_W3 + (((kc * 4 + p0) * 32) + lane) * 16);
                uint4 v = *(const uint4*)(smem + OFF_W3 + (((kc * 4 + p1) * 32) + lane) * 16);
                mma_f16(Ca, A3[kc], u.x, u.y);
                mma_f16(Cb, A3[kc], u.z, u.w);
                mma_f16(Cc, A3[kc], v.x, v.y);
                mma_f16(Cd, A3[kc], v.z, v.w);
            }
            *(float2*)(msg + qrow * MSG_STRIDE + 8 * (4 * t) + 2 * m) = make_float2(Ca[0], Ca[1]);
            *(float2*)(msg + (qrow + 8) * MSG_STRIDE + 8 * (4 * t) + 2 * m) = make_float2(Ca[2], Ca[3]);
            *(float2*)(msg + qrow * MSG_STRIDE + 8 * (4 * t + 1) + 2 * m) = make_float2(Cb[0], Cb[1]);
            *(float2*)(msg + (qrow + 8) * MSG_STRIDE + 8 * (4 * t + 1) + 2 * m) = make_float2(Cb[2], Cb[3]);
            *(float2*)(msg + qrow * MSG_STRIDE + 8 * (4 * t + 2) + 2 * m) = make_float2(Cc[0], Cc[1]);
            *(float2*)(msg + (qrow + 8) * MSG_STRIDE + 8 * (4 * t + 2) + 2 * m) = make_float2(Cc[2], Cc[3]);
            *(float2*)(msg + qrow * MSG_STRIDE + 8 * (4 * t + 3) + 2 * m) = make_float2(Cd[0], Cd[1]);
            *(float2*)(msg + (qrow + 8) * MSG_STRIDE + 8 * (4 * t + 3) + 2 * m) = make_float2(Cd[2], Cd[3]);
        }
        __syncwarp();

        // ---- scatter: 16 edges x 16 float4 atomics ----
        #pragma unroll
        for (int it = 0; it < 8; it++) {
            int slot = it * 32 + lane;
            int e = slot >> 4, q = slot & 15;
            float4 v = *(const float4*)(msg + e * MSG_STRIDE + q * 4);
            int dn = __shfl_sync(0xffffffffu, se.y, e);
            atomicAdd(((float4*)(agg + (size_t)dn * 64)) + q, v);
        }
    }
}

extern "C" void kernel_launch(void* const* d_in, const int* in_sizes, int n_in,
                              void* d_out, int out_size)
{
    const float* nf  = (const float*)d_in[0];
    const float* ef  = (const float*)d_in[1];
    const float* stx = (const float*)d_in[2];
    const float* mW1 = (const float*)d_in[3];
    const float* mb1 = (const float*)d_in[4];
    const float* mW2 = (const float*)d_in[5];
    const float* mb2 = (const float*)d_in[6];
    const float* mW3 = (const float*)d_in[7];
    const float* mb3 = (const float*)d_in[8];
    const float* uW1 = (const float*)d_in[9];
    const float* ub1 = (const float*)d_in[10];
    const float* uW2 = (const float*)d_in[11];
    const float* ub2 = (const float*)d_in[12];
    const int*  eidx = (const int*)d_in[13];

    float* out_node = (float*)d_out;
    float* agg      = out_node + (size_t)N_NODES_C * 64;

    cudaFuncSetAttribute(edge_mlp_kernel,
                         cudaFuncAttributeMaxDynamicSharedMemorySize, EDGE_SMEM_BYTES);
    cudaFuncSetAttribute(node_fused_kernel,
                         cudaFuncAttributeMaxDynamicSharedMemorySize, NODEF_SMEM_BYTES);

    int dev = 0;
    cudaGetDevice(&dev);
    int sms = 148;
    cudaDeviceGetAttribute(&sms, cudaDevAttrMultiProcessorCount, dev);

    node_fused_kernel<<<sms, TPB_N, NODEF_SMEM_BYTES>>>(nf, stx, mW1, uW1, ub1, uW2, ub2,
                                                        out_node, agg);
    edge_mlp_kernel<<<sms, TPB_E, EDGE_SMEM_BYTES>>>(ef, mW1, mb1, mW2, mb2,
                                                     mW3, mb3, eidx, agg);
}